// round 2
// baseline (speedup 1.0000x reference)
#include <cuda_runtime.h>

#define BB 32
#define CC 256
#define TT 1024
#define QKVW 384
#define MT (BB*TT)          // 32768 rows

typedef unsigned long long u64;

__device__ __forceinline__ u64 pk2(float a, float b) {
    u64 r; asm("mov.b64 %0,{%1,%2};" : "=l"(r) : "f"(a), "f"(b)); return r;
}
__device__ __forceinline__ void up2(u64 v, float& a, float& b) {
    asm("mov.b64 {%0,%1},%2;" : "=f"(a), "=f"(b) : "l"(v));
}
__device__ __forceinline__ void ffma2(u64& d, u64 a, u64 b) {
    asm("fma.rn.f32x2 %0,%1,%2,%0;" : "+l"(d) : "l"(a), "l"(b));
}

// ---------------- scratch (device globals; no allocations allowed) ----------
__device__ float g_wcat[CC*QKVW];            // [c, n] concat wq|wk|wv
__device__ float g_bcat[QKVW];
__device__ float g_qkv[(size_t)MT*QKVW];     // [b*T+t, 384]  q|k|v
__device__ float g_st[(size_t)BB*TT*TT];     // scores^T then attn^T: [b, j(key), i(query)]
__device__ float g_m[MT];                    // per (b, j) column max
__device__ float g_rz[MT];                   // per (b, j) 1/sumexp
__device__ float g_rowsum[MT];               // sum_k attn[b, q, k]
__device__ float g_wx[MT];                   // weight_x
__device__ float g_h1[(size_t)MT*CC];        // out_attn [b*T+t, c]
__device__ float g_h2[(size_t)MT*CC];        // conv1 out
__device__ float g_w1t[3*CC*CC];             // [(k*256+i), o] normalized
__device__ float g_w2t[3*CC*CC];

// ---------------- prep kernels ----------------------------------------------
__global__ void k_prep_wcat(const float* __restrict__ wq, const float* __restrict__ bq,
                            const float* __restrict__ wk, const float* __restrict__ bk,
                            const float* __restrict__ wv, const float* __restrict__ bv) {
    int idx = blockIdx.x * blockDim.x + threadIdx.x;
    if (idx < CC*QKVW) {
        int c = idx / QKVW, n = idx % QKVW;
        float w;
        if (n < 64)       w = wq[c*64 + n];
        else if (n < 128) w = wk[c*64 + (n-64)];
        else              w = wv[c*256 + (n-128)];
        g_wcat[idx] = w;
    }
    if (idx < QKVW) {
        int n = idx;
        g_bcat[n] = (n < 64) ? bq[n] : (n < 128) ? bk[n-64] : bv[n-128];
    }
}

__global__ void k_prep_convw(const float* __restrict__ v1, const float* __restrict__ g1,
                             const float* __restrict__ v2, const float* __restrict__ g2) {
    int layer = blockIdx.x >> 8;
    int o = blockIdx.x & 255;
    const float* v = layer ? v2 : v1;
    const float* g = layer ? g2 : g1;
    float* wt = layer ? g_w2t : g_w1t;
    int tid = threadIdx.x;   // 256, one per in-channel i
    float vv[3];
    float part = 0.f;
#pragma unroll
    for (int k = 0; k < 3; k++) {
        vv[k] = v[((size_t)o*CC + tid)*3 + k];
        part += vv[k]*vv[k];
    }
    __shared__ float sm[256];
    sm[tid] = part; __syncthreads();
    for (int s = 128; s > 0; s >>= 1) {
        if (tid < s) sm[tid] += sm[tid+s];
        __syncthreads();
    }
    float scale = g[o] * rsqrtf(sm[0]);
#pragma unroll
    for (int k = 0; k < 3; k++)
        wt[(size_t)(k*CC + tid)*CC + o] = scale * vv[k];
}

// FFMA2 mainloop body shared by all GEMMs: A tile duplicated, rows 132 floats.
#define MAINLOOP_STEP(d)                                                     \
    {                                                                        \
        ulonglong2 a0 = *(const ulonglong2*)&as2[d][ty*8];                   \
        ulonglong2 a1 = *(const ulonglong2*)&as2[d][ty*8 + 4];               \
        ulonglong2 bb = *(const ulonglong2*)&bs[d][tx*4];                    \
        ffma2(acc[0][0], a0.x, bb.x); ffma2(acc[0][1], a0.x, bb.y);          \
        ffma2(acc[1][0], a0.y, bb.x); ffma2(acc[1][1], a0.y, bb.y);          \
        ffma2(acc[2][0], a1.x, bb.x); ffma2(acc[2][1], a1.x, bb.y);          \
        ffma2(acc[3][0], a1.y, bb.x); ffma2(acc[3][1], a1.y, bb.y);          \
    }

// ---------------- GEMM 1: qkv = x^T @ wcat + bcat ----------------------------
__global__ void __launch_bounds__(256) k_qkv(const float* __restrict__ x) {
    __shared__ __align__(16) float as2[16][132];  // duplicated A: [c][2*m]
    __shared__ __align__(16) float bs[16][68];    // [c][n]
    int m0 = blockIdx.x * 64;
    int n0 = blockIdx.y * 64;
    int b = m0 / TT, t0 = m0 % TT;
    int tid = threadIdx.x, tx = tid & 15, ty = tid >> 4;
    u64 acc[4][2] = {};
    const float* xb = x + (size_t)b*CC*TT;
    for (int kc = 0; kc < CC; kc += 16) {
#pragma unroll
        for (int r = 0; r < 4; r++) {
            int e = tid + 256*r; int mm = e & 63, c = e >> 6;
            float av = xb[(size_t)(kc + c)*TT + t0 + mm];
            *(u64*)&as2[c][2*mm] = pk2(av, av);
            bs[c][mm] = g_wcat[(size_t)(kc + c)*QKVW + n0 + mm];
        }
        __syncthreads();
#pragma unroll
        for (int d = 0; d < 16; d++) MAINLOOP_STEP(d)
        __syncthreads();
    }
#pragma unroll
    for (int ii = 0; ii < 4; ii++) {
        int m = m0 + ty*4 + ii;
#pragma unroll
        for (int p = 0; p < 2; p++) {
            int n = n0 + tx*4 + 2*p;
            float f0, f1; up2(acc[ii][p], f0, f1);
            g_qkv[(size_t)m*QKVW + n]     = f0 + g_bcat[n];
            g_qkv[(size_t)m*QKVW + n + 1] = f1 + g_bcat[n+1];
        }
    }
}

// ---------------- GEMM 2: st[b,j,i] = (k[j] . q[i]) / 8, lower band only -----
__global__ void __launch_bounds__(256) k_scores() {
    int i0 = blockIdx.x * 64, j0 = blockIdx.y * 64, b = blockIdx.z;
    if (j0 > i0) return;                       // fully masked tile
    __shared__ __align__(16) float as2[16][132]; // k dup: [d][2*j]
    __shared__ __align__(16) float bs[16][68];   // q: [d][i]
    int tid = threadIdx.x, tx = tid & 15, ty = tid >> 4;
    u64 acc[4][2] = {};
    const float* qb = g_qkv + (size_t)b*TT*QKVW;
    for (int kc = 0; kc < 64; kc += 16) {
#pragma unroll
        for (int r = 0; r < 4; r++) {
            int e = tid + 256*r; int d = e & 15, rr = e >> 4;
            float av = qb[(size_t)(j0 + rr)*QKVW + 64 + kc + d];
            *(u64*)&as2[d][2*rr] = pk2(av, av);
            bs[d][rr] = qb[(size_t)(i0 + rr)*QKVW + 0 + kc + d];
        }
        __syncthreads();
#pragma unroll
        for (int d = 0; d < 16; d++) MAINLOOP_STEP(d)
        __syncthreads();
    }
    size_t base = (size_t)b*TT*TT;
#pragma unroll
    for (int ii = 0; ii < 4; ii++) {
        int j = j0 + ty*4 + ii;
#pragma unroll
        for (int p = 0; p < 2; p++) {
            int i = i0 + tx*4 + 2*p;
            float f0, f1; up2(acc[ii][p], f0, f1);
            g_st[base + (size_t)j*TT + i]     = f0 * 0.125f;
            g_st[base + (size_t)j*TT + i + 1] = f1 * 0.125f;
        }
    }
}

// ---------------- per-(b,j) softmax stats over i in [j, T) -------------------
__global__ void k_stats() {
    int row = blockIdx.x;          // b*T + j
    int b = row >> 10, j = row & 1023;
    const float* p = g_st + (size_t)b*TT*TT + (size_t)j*TT;
    int tid = threadIdx.x;         // 128
    __shared__ float sm[128];
    float mx = -1e30f;
    for (int i = j + tid; i < TT; i += 128) mx = fmaxf(mx, p[i]);
    sm[tid] = mx; __syncthreads();
    for (int s = 64; s > 0; s >>= 1) {
        if (tid < s) sm[tid] = fmaxf(sm[tid], sm[tid+s]);
        __syncthreads();
    }
    mx = sm[0]; __syncthreads();
    float sum = 0.f;
    for (int i = j + tid; i < TT; i += 128) sum += __expf(p[i] - mx);
    sm[tid] = sum; __syncthreads();
    for (int s = 64; s > 0; s >>= 1) {
        if (tid < s) sm[tid] += sm[tid+s];
        __syncthreads();
    }
    if (tid == 0) { g_m[row] = mx; g_rz[row] = 1.f / sm[0]; }
}

// ---------------- attn^T in place (zeros in masked part of band) -------------
__global__ void __launch_bounds__(256) k_attn() {
    int i0 = blockIdx.x * 64, j0 = blockIdx.y * 64, b = blockIdx.z;
    if (j0 > i0) return;
    int tid = threadIdx.x;
    int iof = tid & 63, jr = tid >> 6;         // 4 j-rows per pass
    size_t base = (size_t)b*TT*TT;
#pragma unroll 4
    for (int r = 0; r < 16; r++) {
        int j = j0 + jr*16 + r;
        float mj = g_m[b*TT + j];
        float rz = g_rz[b*TT + j];
        size_t idx = base + (size_t)j*TT + i0 + iof;
        int i = i0 + iof;
        float a = 0.f;
        if (i >= j) a = __expf(g_st[idx] - mj) * rz;
        g_st[idx] = a;
    }
}

// ---------------- rowsum[b,i] = sum_j attn^T[b,j,i]  (deterministic) ---------
__global__ void k_rowsum() {
    int i0 = blockIdx.x * 64, b = blockIdx.y;
    int tid = threadIdx.x;
    int il = tid & 63, jr = tid >> 6;
    const float* ab = g_st + (size_t)b*TT*TT;
    float s = 0.f;
    int jmax = i0 + 64;                        // attn zero beyond the band
    for (int j = jr; j < jmax; j += 4) s += ab[(size_t)j*TT + i0 + il];
    __shared__ float sp[4][64];
    sp[jr][il] = s; __syncthreads();
    if (tid < 64)
        g_rowsum[b*TT + i0 + tid] = sp[0][tid] + sp[1][tid] + sp[2][tid] + sp[3][tid];
}

// ---------------- weight_x = softmax_t(rowsum) -------------------------------
__global__ void k_wx() {
    int b = blockIdx.x, tid = threadIdx.x;     // 256 threads, T=1024
    __shared__ float sm[256];
    float v[4], e[4];
    float mx = -1e30f;
#pragma unroll
    for (int r = 0; r < 4; r++) {
        v[r] = g_rowsum[b*TT + tid + r*256];
        mx = fmaxf(mx, v[r]);
    }
    sm[tid] = mx; __syncthreads();
    for (int s = 128; s > 0; s >>= 1) {
        if (tid < s) sm[tid] = fmaxf(sm[tid], sm[tid+s]);
        __syncthreads();
    }
    mx = sm[0]; __syncthreads();
    float sum = 0.f;
#pragma unroll
    for (int r = 0; r < 4; r++) { e[r] = __expf(v[r] - mx); sum += e[r]; }
    sm[tid] = sum; __syncthreads();
    for (int s = 128; s > 0; s >>= 1) {
        if (tid < s) sm[tid] += sm[tid+s];
        __syncthreads();
    }
    float rz = 1.f / sm[0];
#pragma unroll
    for (int r = 0; r < 4; r++) g_wx[b*TT + tid + r*256] = e[r] * rz;
}

// ---------------- GEMM 3: h1[b,i,c] = sum_j attn^T[b,j,i] * v[b,j,c] ---------
__global__ void __launch_bounds__(256) k_av() {
    int m0 = blockIdx.x * 64, n0 = blockIdx.y * 64;
    int b = m0 / TT, i0 = m0 % TT;
    __shared__ __align__(16) float as2[16][132]; // attn^T dup: [j][2*i]
    __shared__ __align__(16) float bs[16][68];   // v: [j][c]
    int tid = threadIdx.x, tx = tid & 15, ty = tid >> 4;
    u64 acc[4][2] = {};
    const float* ab = g_st + (size_t)b*TT*TT;
    const float* vb = g_qkv + (size_t)b*TT*QKVW + 128;
    int jmax = i0 + 64;                        // causal band
    for (int j0 = 0; j0 < jmax; j0 += 16) {
#pragma unroll
        for (int r = 0; r < 4; r++) {
            int e = tid + 256*r; int mm = e & 63, c = e >> 6;
            float av = ab[(size_t)(j0 + c)*TT + i0 + mm];
            *(u64*)&as2[c][2*mm] = pk2(av, av);
            bs[c][mm] = vb[(size_t)(j0 + c)*QKVW + n0 + mm];
        }
        __syncthreads();
#pragma unroll
        for (int d = 0; d < 16; d++) MAINLOOP_STEP(d)
        __syncthreads();
    }
#pragma unroll
    for (int ii = 0; ii < 4; ii++) {
        int m = m0 + ty*4 + ii;
#pragma unroll
        for (int p = 0; p < 2; p++) {
            int n = n0 + tx*4 + 2*p;
            float f0, f1; up2(acc[ii][p], f0, f1);
            g_h1[(size_t)m*CC + n]     = f0;
            g_h1[(size_t)m*CC + n + 1] = f1;
        }
    }
}

// ---------------- causal conv as K=768 GEMM; mode1 fuses final epilogue ------
__global__ void __launch_bounds__(256) k_conv(int mode,
                                              const float* __restrict__ bias,
                                              const float* __restrict__ x,
                                              float* __restrict__ outp) {
    const float* h  = (mode == 0) ? g_h1  : g_h2;
    const float* wt = (mode == 0) ? g_w1t : g_w2t;
    int m0 = blockIdx.x * 64, n0 = blockIdx.y * 64;
    int b = m0 / TT, t0 = m0 % TT;
    __shared__ __align__(16) float as2[16][132]; // h dup: [i_sub][2*t]
    __shared__ __align__(16) float bs[16][68];   // wt: [i_sub][o]
    int tid = threadIdx.x, tx = tid & 15, ty = tid >> 4;
    u64 acc[4][2] = {};
    for (int kc = 0; kc < 48; kc++) {
        int k = kc >> 4, io = (kc & 15) << 4;
#pragma unroll
        for (int r = 0; r < 4; r++) {
            int e = tid + 256*r; int d = e & 15, mm = e >> 4;
            int tt2 = t0 + mm - 2 + k;
            float av = (tt2 >= 0) ? h[((size_t)b*TT + tt2)*CC + io + d] : 0.f;
            *(u64*)&as2[d][2*mm] = pk2(av, av);
        }
#pragma unroll
        for (int r = 0; r < 4; r++) {
            int e = tid + 256*r; int nn = e & 63, d = e >> 6;
            bs[d][nn] = wt[(size_t)(kc*16 + d)*CC + n0 + nn];
        }
        __syncthreads();
#pragma unroll
        for (int d = 0; d < 16; d++) MAINLOOP_STEP(d)
        __syncthreads();
    }
    if (mode == 0) {
#pragma unroll
        for (int ii = 0; ii < 4; ii++) {
            int m = m0 + ty*4 + ii;
#pragma unroll
            for (int p = 0; p < 2; p++) {
                int n = n0 + tx*4 + 2*p;
                float f0, f1; up2(acc[ii][p], f0, f1);
                g_h2[(size_t)m*CC + n]     = fmaxf(f0 + bias[n], 0.f);
                g_h2[(size_t)m*CC + n + 1] = fmaxf(f1 + bias[n+1], 0.f);
            }
        }
    } else {
#pragma unroll
        for (int ii = 0; ii < 4; ii++) {
            int t = t0 + ty*4 + ii;
            float wxv = g_wx[b*TT + t];
#pragma unroll
            for (int p = 0; p < 2; p++) {
                int n = n0 + tx*4 + 2*p;
                float f0, f1; up2(acc[ii][p], f0, f1);
                {
                    float cv = fmaxf(f0 + bias[n], 0.f);
                    size_t oidx = (size_t)b*CC*TT + (size_t)n*TT + t;
                    outp[oidx] = fmaxf(cv + x[oidx] * (1.f + wxv), 0.f);
                }
                {
                    float cv = fmaxf(f1 + bias[n+1], 0.f);
                    size_t oidx = (size_t)b*CC*TT + (size_t)(n+1)*TT + t;
                    outp[oidx] = fmaxf(cv + x[oidx] * (1.f + wxv), 0.f);
                }
            }
        }
    }
}

// ---------------- launch ------------------------------------------------------
extern "C" void kernel_launch(void* const* d_in, const int* in_sizes, int n_in,
                              void* d_out, int out_size) {
    const float* x  = (const float*)d_in[0];
    const float* wq = (const float*)d_in[1];
    const float* bq = (const float*)d_in[2];
    const float* wk = (const float*)d_in[3];
    const float* bk = (const float*)d_in[4];
    const float* wv = (const float*)d_in[5];
    const float* bv = (const float*)d_in[6];
    const float* v1 = (const float*)d_in[7];
    const float* g1 = (const float*)d_in[8];
    const float* b1 = (const float*)d_in[9];
    const float* v2 = (const float*)d_in[10];
    const float* g2 = (const float*)d_in[11];
    const float* b2 = (const float*)d_in[12];
    float* out = (float*)d_out;

    k_prep_wcat<<<(CC*QKVW + 255)/256, 256>>>(wq, bq, wk, bk, wv, bv);
    k_prep_convw<<<512, 256>>>(v1, g1, v2, g2);
    k_qkv<<<dim3(MT/64, QKVW/64), 256>>>(x);
    k_scores<<<dim3(16, 16, BB), 256>>>();
    k_stats<<<MT, 128>>>();
    k_attn<<<dim3(16, 16, BB), 256>>>();
    k_rowsum<<<dim3(16, BB), 256>>>();
    k_wx<<<BB, 256>>>();
    k_av<<<dim3(MT/64, CC/64), 256>>>();
    k_conv<<<dim3(MT/64, CC/64), 256>>>(0, b1, x, out);
    k_conv<<<dim3(MT/64, CC/64), 256>>>(1, b2, x, out);
}

// round 4
// speedup vs baseline: 1.7699x; 1.7699x over previous
#include <cuda_runtime.h>
#include <cuda_bf16.h>
#include <cstdint>

#define BB 32
#define CC 256
#define TT 1024
#define QKVW 384
#define MT (BB*TT)          // 32768 rows
#define CONVK 768

typedef uint32_t u32;

// ---------------- scratch (device globals; no allocations allowed) ----------
__device__ float g_wcat[CC*QKVW];            // [c, n] concat wq|wk|wv
__device__ float g_bcat[QKVW];
__device__ float g_qkv[(size_t)MT*QKVW];     // [b*T+t, 384]  q|k|v
__device__ float g_st[(size_t)BB*TT*TT];     // scores^T then attn^T: [b, j, i]
__device__ float g_m[MT];
__device__ float g_rz[MT];
__device__ float g_rowsum[MT];
__device__ float g_wx[MT];
// bf16 split operands for tensor-core convs
__device__ __align__(16) __nv_bfloat16 g_h1h[(size_t)MT*CC];
__device__ __align__(16) __nv_bfloat16 g_h1l[(size_t)MT*CC];
__device__ __align__(16) __nv_bfloat16 g_h2h[(size_t)MT*CC];
__device__ __align__(16) __nv_bfloat16 g_h2l[(size_t)MT*CC];
__device__ __align__(16) __nv_bfloat16 g_w1bh[CC*CONVK];   // [o, koff*256+i]
__device__ __align__(16) __nv_bfloat16 g_w1bl[CC*CONVK];
__device__ __align__(16) __nv_bfloat16 g_w2bh[CC*CONVK];
__device__ __align__(16) __nv_bfloat16 g_w2bl[CC*CONVK];

// ---------------- helpers ----------------------------------------------------
__device__ __forceinline__ u32 smem_u32(const void* p) {
    u32 a;
    asm("{ .reg .u64 t; cvta.to.shared.u64 t, %1; cvt.u32.u64 %0, t; }"
        : "=r"(a) : "l"(p));
    return a;
}
__device__ __forceinline__ void cp16(u32 dst, const void* src, bool ok) {
    int sz = ok ? 16 : 0;
    asm volatile("cp.async.cg.shared.global [%0], [%1], 16, %2;"
                 :: "r"(dst), "l"(src), "r"(sz) : "memory");
}
#define CP_COMMIT() asm volatile("cp.async.commit_group;" ::: "memory")
#define CP_WAIT(n)  asm volatile("cp.async.wait_group %0;" :: "n"(n) : "memory")

__device__ __forceinline__ void mma16816(float c[4], const u32 a[4], const u32 b[2]) {
    asm volatile(
        "mma.sync.aligned.m16n8k16.row.col.f32.bf16.bf16.f32 "
        "{%0,%1,%2,%3}, {%4,%5,%6,%7}, {%8,%9}, {%0,%1,%2,%3};"
        : "+f"(c[0]), "+f"(c[1]), "+f"(c[2]), "+f"(c[3])
        : "r"(a[0]), "r"(a[1]), "r"(a[2]), "r"(a[3]), "r"(b[0]), "r"(b[1]));
}

__device__ __forceinline__ void bf16_split(float v, __nv_bfloat16& h, __nv_bfloat16& l) {
    h = __float2bfloat16(v);
    l = __float2bfloat16(v - __bfloat162float(h));
}

// ---------------- prep kernels ----------------------------------------------
__global__ void k_prep_wcat(const float* __restrict__ wq, const float* __restrict__ bq,
                            const float* __restrict__ wk, const float* __restrict__ bk,
                            const float* __restrict__ wv, const float* __restrict__ bv) {
    int idx = blockIdx.x * blockDim.x + threadIdx.x;
    if (idx < CC*QKVW) {
        int c = idx / QKVW, n = idx % QKVW;
        float w;
        if (n < 64)       w = wq[c*64 + n];
        else if (n < 128) w = wk[c*64 + (n-64)];
        else              w = wv[c*256 + (n-128)];
        g_wcat[idx] = w;
    }
    if (idx < QKVW) {
        int n = idx;
        g_bcat[n] = (n < 64) ? bq[n] : (n < 128) ? bk[n-64] : bv[n-128];
    }
}

// weight-norm + K-major bf16-split conv weights: wb[o, koff*256+i]
__global__ void k_prep_convw(const float* __restrict__ v1, const float* __restrict__ g1,
                             const float* __restrict__ v2, const float* __restrict__ g2) {
    int layer = blockIdx.x >> 8;
    int o = blockIdx.x & 255;
    const float* v = layer ? v2 : v1;
    const float* g = layer ? g2 : g1;
    __nv_bfloat16* wh = layer ? g_w2bh : g_w1bh;
    __nv_bfloat16* wl = layer ? g_w2bl : g_w1bl;
    int tid = threadIdx.x;   // 256, one per in-channel i
    float vv[3];
    float part = 0.f;
#pragma unroll
    for (int k = 0; k < 3; k++) {
        vv[k] = v[((size_t)o*CC + tid)*3 + k];
        part += vv[k]*vv[k];
    }
    __shared__ float sm[256];
    sm[tid] = part; __syncthreads();
    for (int s = 128; s > 0; s >>= 1) {
        if (tid < s) sm[tid] += sm[tid+s];
        __syncthreads();
    }
    float scale = g[o] * rsqrtf(sm[0]);
#pragma unroll
    for (int k = 0; k < 3; k++) {
        float w = scale * vv[k];
        __nv_bfloat16 h, l; bf16_split(w, h, l);
        wh[(size_t)o*CONVK + k*CC + tid] = h;
        wl[(size_t)o*CONVK + k*CC + tid] = l;
    }
}

// ---------------- GEMM 1: qkv = x^T @ wcat + bcat (scalar) -------------------
__global__ void __launch_bounds__(256) k_qkv(const float* __restrict__ x) {
    __shared__ float as[16][64];
    __shared__ float bs[16][64];
    int m0 = blockIdx.x * 64;
    int n0 = blockIdx.y * 64;
    int b = m0 / TT, t0 = m0 % TT;
    int tid = threadIdx.x, tx = tid & 15, ty = tid >> 4;
    float acc[4][4] = {};
    const float* xb = x + (size_t)b*CC*TT;
    for (int kc = 0; kc < CC; kc += 16) {
#pragma unroll
        for (int r = 0; r < 4; r++) {
            int e = tid + 256*r; int mm = e & 63, c = e >> 6;
            as[c][mm] = xb[(size_t)(kc + c)*TT + t0 + mm];
            bs[c][mm] = g_wcat[(size_t)(kc + c)*QKVW + n0 + mm];
        }
        __syncthreads();
#pragma unroll
        for (int d = 0; d < 16; d++) {
            float4 a4 = *(const float4*)&as[d][ty*4];
            float4 b4 = *(const float4*)&bs[d][tx*4];
            float av[4] = {a4.x,a4.y,a4.z,a4.w};
            float bv[4] = {b4.x,b4.y,b4.z,b4.w};
#pragma unroll
            for (int ii = 0; ii < 4; ii++)
#pragma unroll
                for (int jj = 0; jj < 4; jj++)
                    acc[ii][jj] += av[ii]*bv[jj];
        }
        __syncthreads();
    }
#pragma unroll
    for (int ii = 0; ii < 4; ii++) {
        int m = m0 + ty*4 + ii;
#pragma unroll
        for (int jj = 0; jj < 4; jj++) {
            int n = n0 + tx*4 + jj;
            g_qkv[(size_t)m*QKVW + n] = acc[ii][jj] + g_bcat[n];
        }
    }
}

// ---------------- GEMM 2: st[b,j,i] = (k[j].q[i])/8, lower band only ---------
__global__ void __launch_bounds__(256) k_scores() {
    int i0 = blockIdx.x * 64, j0 = blockIdx.y * 64, b = blockIdx.z;
    if (j0 > i0) return;
    __shared__ float as[16][68];
    __shared__ float bs[16][68];
    int tid = threadIdx.x, tx = tid & 15, ty = tid >> 4;
    float acc[4][4] = {};
    const float* qb = g_qkv + (size_t)b*TT*QKVW;
    for (int kc = 0; kc < 64; kc += 16) {
#pragma unroll
        for (int r = 0; r < 4; r++) {
            int e = tid + 256*r; int d = e & 15, rr = e >> 4;
            as[d][rr] = qb[(size_t)(j0 + rr)*QKVW + 64 + kc + d];
            bs[d][rr] = qb[(size_t)(i0 + rr)*QKVW +  0 + kc + d];
        }
        __syncthreads();
#pragma unroll
        for (int d = 0; d < 16; d++) {
            float4 a4 = *(const float4*)&as[d][ty*4];
            float4 b4 = *(const float4*)&bs[d][tx*4];
            float av[4] = {a4.x,a4.y,a4.z,a4.w};
            float bv[4] = {b4.x,b4.y,b4.z,b4.w};
#pragma unroll
            for (int ii = 0; ii < 4; ii++)
#pragma unroll
                for (int jj = 0; jj < 4; jj++)
                    acc[ii][jj] += av[ii]*bv[jj];
        }
        __syncthreads();
    }
    size_t base = (size_t)b*TT*TT;
#pragma unroll
    for (int ii = 0; ii < 4; ii++) {
        int j = j0 + ty*4 + ii;
#pragma unroll
        for (int jj = 0; jj < 4; jj++) {
            int i = i0 + tx*4 + jj;
            g_st[base + (size_t)j*TT + i] = acc[ii][jj] * 0.125f;
        }
    }
}

// ---------------- per-(b,j) softmax stats over i in [j, T) -------------------
__global__ void k_stats() {
    int row = blockIdx.x;
    int b = row >> 10, j = row & 1023;
    const float* p = g_st + (size_t)b*TT*TT + (size_t)j*TT;
    int tid = threadIdx.x;
    __shared__ float sm[128];
    float mx = -1e30f;
    for (int i = j + tid; i < TT; i += 128) mx = fmaxf(mx, p[i]);
    sm[tid] = mx; __syncthreads();
    for (int s = 64; s > 0; s >>= 1) {
        if (tid < s) sm[tid] = fmaxf(sm[tid], sm[tid+s]);
        __syncthreads();
    }
    mx = sm[0]; __syncthreads();
    float sum = 0.f;
    for (int i = j + tid; i < TT; i += 128) sum += __expf(p[i] - mx);
    sm[tid] = sum; __syncthreads();
    for (int s = 64; s > 0; s >>= 1) {
        if (tid < s) sm[tid] += sm[tid+s];
        __syncthreads();
    }
    if (tid == 0) { g_m[row] = mx; g_rz[row] = 1.f / sm[0]; }
}

// ---------------- attn^T in place --------------------------------------------
__global__ void __launch_bounds__(256) k_attn() {
    int i0 = blockIdx.x * 64, j0 = blockIdx.y * 64, b = blockIdx.z;
    if (j0 > i0) return;
    int tid = threadIdx.x;
    int iof = tid & 63, jr = tid >> 6;
    size_t base = (size_t)b*TT*TT;
#pragma unroll 4
    for (int r = 0; r < 16; r++) {
        int j = j0 + jr*16 + r;
        float mj = g_m[b*TT + j];
        float rz = g_rz[b*TT + j];
        size_t idx = base + (size_t)j*TT + i0 + iof;
        int i = i0 + iof;
        float a = 0.f;
        if (i >= j) a = __expf(g_st[idx] - mj) * rz;
        g_st[idx] = a;
    }
}

// ---------------- rowsum[b,i] = sum_j attn^T[b,j,i] --------------------------
__global__ void k_rowsum() {
    int i0 = blockIdx.x * 64, b = blockIdx.y;
    int tid = threadIdx.x;
    int il = tid & 63, jr = tid >> 6;
    const float* ab = g_st + (size_t)b*TT*TT;
    float s = 0.f;
    int jmax = i0 + 64;
    for (int j = jr; j < jmax; j += 4) s += ab[(size_t)j*TT + i0 + il];
    __shared__ float sp[4][64];
    sp[jr][il] = s; __syncthreads();
    if (tid < 64)
        g_rowsum[b*TT + i0 + tid] = sp[0][tid] + sp[1][tid] + sp[2][tid] + sp[3][tid];
}

// ---------------- weight_x = softmax_t(rowsum) -------------------------------
__global__ void k_wx() {
    int b = blockIdx.x, tid = threadIdx.x;
    __shared__ float sm[256];
    float v[4], e[4];
    float mx = -1e30f;
#pragma unroll
    for (int r = 0; r < 4; r++) {
        v[r] = g_rowsum[b*TT + tid + r*256];
        mx = fmaxf(mx, v[r]);
    }
    sm[tid] = mx; __syncthreads();
    for (int s = 128; s > 0; s >>= 1) {
        if (tid < s) sm[tid] = fmaxf(sm[tid], sm[tid+s]);
        __syncthreads();
    }
    mx = sm[0]; __syncthreads();
    float sum = 0.f;
#pragma unroll
    for (int r = 0; r < 4; r++) { e[r] = __expf(v[r] - mx); sum += e[r]; }
    sm[tid] = sum; __syncthreads();
    for (int s = 128; s > 0; s >>= 1) {
        if (tid < s) sm[tid] += sm[tid+s];
        __syncthreads();
    }
    float rz = 1.f / sm[0];
#pragma unroll
    for (int r = 0; r < 4; r++) g_wx[b*TT + tid + r*256] = e[r] * rz;
}

// ---------------- GEMM 3: h1 = attn @ v; epilogue writes bf16 splits ---------
__global__ void __launch_bounds__(256) k_av() {
    int m0 = blockIdx.x * 64, n0 = blockIdx.y * 64;
    int b = m0 / TT, i0 = m0 % TT;
    __shared__ float as[16][64];
    __shared__ float bs[16][64];
    int tid = threadIdx.x, tx = tid & 15, ty = tid >> 4;
    float acc[4][4] = {};
    const float* ab = g_st + (size_t)b*TT*TT;
    const float* vb = g_qkv + (size_t)b*TT*QKVW + 128;
    int jmax = i0 + 64;
    for (int j0 = 0; j0 < jmax; j0 += 16) {
#pragma unroll
        for (int r = 0; r < 4; r++) {
            int e = tid + 256*r; int mm = e & 63, c = e >> 6;
            as[c][mm] = ab[(size_t)(j0 + c)*TT + i0 + mm];
            bs[c][mm] = vb[(size_t)(j0 + c)*QKVW + n0 + mm];
        }
        __syncthreads();
#pragma unroll
        for (int d = 0; d < 16; d++) {
            float4 a4 = *(const float4*)&as[d][ty*4];
            float4 b4 = *(const float4*)&bs[d][tx*4];
            float av[4] = {a4.x,a4.y,a4.z,a4.w};
            float bv[4] = {b4.x,b4.y,b4.z,b4.w};
#pragma unroll
            for (int ii = 0; ii < 4; ii++)
#pragma unroll
                for (int jj = 0; jj < 4; jj++)
                    acc[ii][jj] += av[ii]*bv[jj];
        }
        __syncthreads();
    }
#pragma unroll
    for (int ii = 0; ii < 4; ii++) {
        int m = m0 + ty*4 + ii;
#pragma unroll
        for (int jj = 0; jj < 4; jj += 2) {
            size_t idx = (size_t)m*CC + n0 + tx*4 + jj;
            __nv_bfloat16 h0, l0, h1, l1;
            bf16_split(acc[ii][jj],   h0, l0);
            bf16_split(acc[ii][jj+1], h1, l1);
            *(__nv_bfloat162*)&g_h1h[idx] = __nv_bfloat162(h0, h1);
            *(__nv_bfloat162*)&g_h1l[idx] = __nv_bfloat162(l0, l1);
        }
    }
}

// ---------------- tensor-core conv: mma.sync bf16, 3-product split -----------
// CTA: 128 (t) x 128 (o). 8 warps, each 32x64. K = 768 in 24 chunks of 32.
// Smem per stage: Ah|Al|Bh|Bl, each 128 rows x 40 bf16 (80 B padded stride).
#define ROWB 80
#define MATB (128*ROWB)      // 10240 B
#define STG  (4*MATB)        // 40960 B
#define CONV_SMEM (2*STG)    // 81920 B

__global__ void __launch_bounds__(256) k_conv_mma(int mode,
                                                  const float* __restrict__ bias,
                                                  const float* __restrict__ x,
                                                  float* __restrict__ outp) {
    extern __shared__ __align__(16) char smem[];
    const __nv_bfloat16* Ahp = mode ? g_h2h  : g_h1h;
    const __nv_bfloat16* Alp = mode ? g_h2l  : g_h1l;
    const __nv_bfloat16* Bhp = mode ? g_w2bh : g_w1bh;
    const __nv_bfloat16* Blp = mode ? g_w2bl : g_w1bl;

    int m0 = blockIdx.x * 128;
    int n0 = blockIdx.y * 128;
    int b = m0 / TT, t0 = m0 % TT;
    int tid = threadIdx.x;
    int wid = tid >> 5, lane = tid & 31;
    int warp_m = wid & 3, warp_n = wid >> 2;
    int g = lane >> 2, tg = lane & 3;

    u32 sbase = smem_u32(smem);
    int lrow = tid >> 1, lhalf = tid & 1;   // loader mapping

    float acc[2][8][4];
#pragma unroll
    for (int a = 0; a < 2; a++)
#pragma unroll
        for (int c = 0; c < 8; c++)
#pragma unroll
            for (int d = 0; d < 4; d++) acc[a][c][d] = 0.f;

    // ---- async load of chunk cc into stage s ----
    auto issue = [&](int cc, int s) {
        int koff = cc >> 3, i0c = (cc & 7) * 32;
        int t = t0 + lrow + koff - 2;
        bool ok = (t >= 0);
        size_t ga = (size_t)(b*TT + t)*CC + i0c + lhalf*16;
        size_t gb = (size_t)(n0 + lrow)*CONVK + cc*32 + lhalf*16;
        u32 d0 = sbase + s*STG + lrow*ROWB + lhalf*32;
        cp16(d0,            Ahp + ga,     ok);
        cp16(d0 + 16,       Ahp + ga + 8, ok);
        cp16(d0 + MATB,     Alp + ga,     ok);
        cp16(d0 + MATB+16,  Alp + ga + 8, ok);
        cp16(d0 + 2*MATB,    Bhp + gb,     true);
        cp16(d0 + 2*MATB+16, Bhp + gb + 8, true);
        cp16(d0 + 3*MATB,    Blp + gb,     true);
        cp16(d0 + 3*MATB+16, Blp + gb + 8, true);
    };

    issue(0, 0);
    CP_COMMIT();

    for (int cc = 0; cc < 24; cc++) {
        int s = cc & 1;
        if (cc < 23) {
            issue(cc + 1, s ^ 1);
            CP_COMMIT();
            CP_WAIT(1);
        } else {
            CP_WAIT(0);
        }
        __syncthreads();
        const char* Ah = smem + s*STG;
        const char* Al = Ah + MATB;
        const char* Bh = Ah + 2*MATB;
        const char* Bl = Ah + 3*MATB;
#pragma unroll
        for (int ks = 0; ks < 2; ks++) {
            u32 ah[2][4], al[2][4];
#pragma unroll
            for (int mt = 0; mt < 2; mt++) {
                int o0 = (warp_m*32 + mt*16 + g)*ROWB + ks*32 + tg*4;
                ah[mt][0] = *(const u32*)(Ah + o0);
                ah[mt][1] = *(const u32*)(Ah + o0 + 8*ROWB);
                ah[mt][2] = *(const u32*)(Ah + o0 + 16);
                ah[mt][3] = *(const u32*)(Ah + o0 + 8*ROWB + 16);
                al[mt][0] = *(const u32*)(Al + o0);
                al[mt][1] = *(const u32*)(Al + o0 + 8*ROWB);
                al[mt][2] = *(const u32*)(Al + o0 + 16);
                al[mt][3] = *(const u32*)(Al + o0 + 8*ROWB + 16);
            }
            u32 bh[8][2], bl[8][2];
#pragma unroll
            for (int nt = 0; nt < 8; nt++) {
                int o0 = (warp_n*64 + nt*8 + g)*ROWB + ks*32 + tg*4;
                bh[nt][0] = *(const u32*)(Bh + o0);
                bh[nt][1] = *(const u32*)(Bh + o0 + 16);
                bl[nt][0] = *(const u32*)(Bl + o0);
                bl[nt][1] = *(const u32*)(Bl + o0 + 16);
            }
#pragma unroll
            for (int mt = 0; mt < 2; mt++)
#pragma unroll
                for (int nt = 0; nt < 8; nt++) {
                    mma16816(acc[mt][nt], ah[mt], bh[nt]);
                    mma16816(acc[mt][nt], ah[mt], bl[nt]);
                    mma16816(acc[mt][nt], al[mt], bh[nt]);
                }
        }
        __syncthreads();
    }

    // ---- epilogue ----
#pragma unroll
    for (int mt = 0; mt < 2; mt++) {
        int t_lo = t0 + warp_m*32 + mt*16 + g;
        int t_hi = t_lo + 8;
        if (mode == 0) {
#pragma unroll
            for (int nt = 0; nt < 8; nt++) {
                int n = n0 + warp_n*64 + nt*8 + tg*2;
                float b0 = bias[n], b1 = bias[n+1];
                float* c = acc[mt][nt];
                float v0 = fmaxf(c[0] + b0, 0.f);
                float v1 = fmaxf(c[1] + b1, 0.f);
                float v2 = fmaxf(c[2] + b0, 0.f);
                float v3 = fmaxf(c[3] + b1, 0.f);
                __nv_bfloat16 h0,l0,h1,l1;
                bf16_split(v0, h0, l0); bf16_split(v1, h1, l1);
                size_t i_lo = (size_t)(b*TT + t_lo)*CC + n;
                *(__nv_bfloat162*)&g_h2h[i_lo] = __nv_bfloat162(h0, h1);
                *(__nv_bfloat162*)&g_h2l[i_lo] = __nv_bfloat162(l0, l1);
                bf16_split(v2, h0, l0); bf16_split(v3, h1, l1);
                size_t i_hi = (size_t)(b*TT + t_hi)*CC + n;
                *(__nv_bfloat162*)&g_h2h[i_hi] = __nv_bfloat162(h0, h1);
                *(__nv_bfloat162*)&g_h2l[i_hi] = __nv_bfloat162(l0, l1);
            }
        } else {
            float w_lo = 1.f + g_wx[b*TT + t_lo];
            float w_hi = 1.f + g_wx[b*TT + t_hi];
#pragma unroll
            for (int nt = 0; nt < 8; nt++) {
                int n = n0 + warp_n*64 + nt*8 + tg*2;
                float b0 = bias[n], b1 = bias[n+1];
                float* c = acc[mt][nt];
                size_t o00 = ((size_t)b*CC + n)*TT + t_lo;
                size_t o10 = o00 + TT;          // n+1, t_lo
                size_t o01 = o00 + 8;           // n,   t_hi
                size_t o11 = o10 + 8;           // n+1, t_hi
                outp[o00] = fmaxf(fmaxf(c[0] + b0, 0.f) + x[o00]*w_lo, 0.f);
                outp[o10] = fmaxf(fmaxf(c[1] + b1, 0.f) + x[o10]*w_lo, 0.f);
                outp[o01] = fmaxf(fmaxf(c[2] + b0, 0.f) + x[o01]*w_hi, 0.f);
                outp[o11] = fmaxf(fmaxf(c[3] + b1, 0.f) + x[o11]*w_hi, 0.f);
            }
        }
    }
}

// ---------------- launch ------------------------------------------------------
extern "C" void kernel_launch(void* const* d_in, const int* in_sizes, int n_in,
                              void* d_out, int out_size) {
    const float* x  = (const float*)d_in[0];
    const float* wq = (const float*)d_in[1];
    const float* bq = (const float*)d_in[2];
    const float* wk = (const float*)d_in[3];
    const float* bk = (const float*)d_in[4];
    const float* wv = (const float*)d_in[5];
    const float* bv = (const float*)d_in[6];
    const float* v1 = (const float*)d_in[7];
    const float* g1 = (const float*)d_in[8];
    const float* b1 = (const float*)d_in[9];
    const float* v2 = (const float*)d_in[10];
    const float* g2 = (const float*)d_in[11];
    const float* b2 = (const float*)d_in[12];
    float* out = (float*)d_out;

    static int smset = 0;
    if (!smset) {
        cudaFuncSetAttribute(k_conv_mma, cudaFuncAttributeMaxDynamicSharedMemorySize, CONV_SMEM);
        smset = 1;
    }

    k_prep_wcat<<<(CC*QKVW + 255)/256, 256>>>(wq, bq, wk, bk, wv, bv);
    k_prep_convw<<<512, 256>>>(v1, g1, v2, g2);
    k_qkv<<<dim3(MT/64, QKVW/64), 256>>>(x);
    k_scores<<<dim3(16, 16, BB), 256>>>();
    k_stats<<<MT, 128>>>();
    k_attn<<<dim3(16, 16, BB), 256>>>();
    k_rowsum<<<dim3(16, BB), 256>>>();
    k_wx<<<BB, 256>>>();
    k_av<<<dim3(MT/64, CC/64), 256>>>();
    k_conv_mma<<<dim3(MT/128, CC/128), 256, CONV_SMEM>>>(0, b1, x, out);
    k_conv_mma<<<dim3(MT/128, CC/128), 256, CONV_SMEM>>>(1, b2, x, out);
}

// round 5
// speedup vs baseline: 2.4315x; 1.3738x over previous
#include <cuda_runtime.h>
#include <cuda_bf16.h>
#include <cstdint>

#define BB 32
#define CC 256
#define TT 1024
#define QKVW 384
#define MT (BB*TT)
#define CONVK 768

typedef uint32_t u32;

// ---------------- scratch (device globals; zero-initialized BSS) -------------
__device__ float g_bcat[QKVW];
__device__ float g_st[(size_t)BB*TT*TT];     // scores [b][j][i]
__device__ float g_m[MT];
__device__ float g_rz[MT];
__device__ float g_rowsum[MT];
__device__ float g_wx[MT];
// bf16 split operands
__device__ __align__(16) __nv_bfloat16 g_xth[(size_t)MT*CC];  // x^T [t][c]
__device__ __align__(16) __nv_bfloat16 g_xtl[(size_t)MT*CC];
__device__ __align__(16) __nv_bfloat16 g_wcbh[QKVW*CC];       // wcat^T [n][c]
__device__ __align__(16) __nv_bfloat16 g_wcbl[QKVW*CC];
__device__ __align__(16) __nv_bfloat16 g_qh[(size_t)MT*64];
__device__ __align__(16) __nv_bfloat16 g_ql[(size_t)MT*64];
__device__ __align__(16) __nv_bfloat16 g_kh[(size_t)MT*64];
__device__ __align__(16) __nv_bfloat16 g_kl[(size_t)MT*64];
__device__ __align__(16) __nv_bfloat16 g_vth[(size_t)BB*CC*TT]; // v^T [b][c][t]
__device__ __align__(16) __nv_bfloat16 g_vtl[(size_t)BB*CC*TT];
__device__ __align__(16) __nv_bfloat16 g_ath[(size_t)BB*TT*TT]; // attn [b][i][j]
__device__ __align__(16) __nv_bfloat16 g_atl[(size_t)BB*TT*TT]; // never-written = 0
__device__ __align__(16) __nv_bfloat16 g_h1h[(size_t)MT*CC];
__device__ __align__(16) __nv_bfloat16 g_h1l[(size_t)MT*CC];
__device__ __align__(16) __nv_bfloat16 g_h2h[(size_t)MT*CC];
__device__ __align__(16) __nv_bfloat16 g_h2l[(size_t)MT*CC];
__device__ __align__(16) __nv_bfloat16 g_w1bh[CC*CONVK];
__device__ __align__(16) __nv_bfloat16 g_w1bl[CC*CONVK];
__device__ __align__(16) __nv_bfloat16 g_w2bh[CC*CONVK];
__device__ __align__(16) __nv_bfloat16 g_w2bl[CC*CONVK];

// ---------------- helpers ----------------------------------------------------
__device__ __forceinline__ u32 smem_u32(const void* p) {
    u32 a;
    asm("{ .reg .u64 t; cvta.to.shared.u64 t, %1; cvt.u32.u64 %0, t; }"
        : "=r"(a) : "l"(p));
    return a;
}
__device__ __forceinline__ void cp16(u32 dst, const void* src, bool ok) {
    int sz = ok ? 16 : 0;
    asm volatile("cp.async.cg.shared.global [%0], [%1], 16, %2;"
                 :: "r"(dst), "l"(src), "r"(sz) : "memory");
}
#define CP_COMMIT() asm volatile("cp.async.commit_group;" ::: "memory")
#define CP_WAIT(n)  asm volatile("cp.async.wait_group %0;" :: "n"(n) : "memory")

__device__ __forceinline__ void mma16816(float c[4], const u32 a[4], const u32 b[2]) {
    asm volatile(
        "mma.sync.aligned.m16n8k16.row.col.f32.bf16.bf16.f32 "
        "{%0,%1,%2,%3}, {%4,%5,%6,%7}, {%8,%9}, {%0,%1,%2,%3};"
        : "+f"(c[0]), "+f"(c[1]), "+f"(c[2]), "+f"(c[3])
        : "r"(a[0]), "r"(a[1]), "r"(a[2]), "r"(a[3]), "r"(b[0]), "r"(b[1]));
}
__device__ __forceinline__ void bf16_split(float v, __nv_bfloat16& h, __nv_bfloat16& l) {
    h = __float2bfloat16(v);
    l = __float2bfloat16(v - __bfloat162float(h));
}

// smem stage geometry (shared by all mma kernels): 4 matrices, 128 rows x 32 bf16
#define ROWB 80
#define MATB (128*ROWB)
#define STG  (4*MATB)
#define MMA_SMEM (2*STG)     // 81920 B

// one K=32 chunk of compute on the current stage
__device__ __forceinline__ void mma_chunk(const char* Ah, const char* Al,
                                          const char* Bh, const char* Bl,
                                          int warp_m, int warp_n, int g, int tg,
                                          float acc[2][8][4]) {
#pragma unroll
    for (int ks = 0; ks < 2; ks++) {
        u32 ah[2][4], al[2][4];
#pragma unroll
        for (int mt = 0; mt < 2; mt++) {
            int o0 = (warp_m*32 + mt*16 + g)*ROWB + ks*32 + tg*4;
            ah[mt][0] = *(const u32*)(Ah + o0);
            ah[mt][1] = *(const u32*)(Ah + o0 + 8*ROWB);
            ah[mt][2] = *(const u32*)(Ah + o0 + 16);
            ah[mt][3] = *(const u32*)(Ah + o0 + 8*ROWB + 16);
            al[mt][0] = *(const u32*)(Al + o0);
            al[mt][1] = *(const u32*)(Al + o0 + 8*ROWB);
            al[mt][2] = *(const u32*)(Al + o0 + 16);
            al[mt][3] = *(const u32*)(Al + o0 + 8*ROWB + 16);
        }
        u32 bh[8][2], bl[8][2];
#pragma unroll
        for (int nt = 0; nt < 8; nt++) {
            int o0 = (warp_n*64 + nt*8 + g)*ROWB + ks*32 + tg*4;
            bh[nt][0] = *(const u32*)(Bh + o0);
            bh[nt][1] = *(const u32*)(Bh + o0 + 16);
            bl[nt][0] = *(const u32*)(Bl + o0);
            bl[nt][1] = *(const u32*)(Bl + o0 + 16);
        }
#pragma unroll
        for (int mt = 0; mt < 2; mt++)
#pragma unroll
            for (int nt = 0; nt < 8; nt++) {
                mma16816(acc[mt][nt], ah[mt], bh[nt]);
                mma16816(acc[mt][nt], ah[mt], bl[nt]);
                mma16816(acc[mt][nt], al[mt], bh[nt]);
            }
    }
}

// ---------------- prep: transpose-split x ------------------------------------
__global__ void k_prep_xt(const float* __restrict__ x) {
    __shared__ float sm[32][33];
    int t0 = blockIdx.x * 32, c0 = blockIdx.y * 32, b = blockIdx.z;
    int lane = threadIdx.x & 31, grp = threadIdx.x >> 5;   // 256 threads
#pragma unroll
    for (int r = 0; r < 4; r++) {
        int c = grp + r*8;
        sm[c][lane] = x[((size_t)b*CC + c0 + c)*TT + t0 + lane];
    }
    __syncthreads();
#pragma unroll
    for (int r = 0; r < 4; r++) {
        int t = grp + r*8;
        float v = sm[lane][t];
        __nv_bfloat16 h, l; bf16_split(v, h, l);
        size_t idx = (size_t)(b*TT + t0 + t)*CC + c0 + lane;
        g_xth[idx] = h; g_xtl[idx] = l;
    }
}

// ---------------- prep: wcat^T split + bcat ----------------------------------
__global__ void k_prep_wcat(const float* __restrict__ wq, const float* __restrict__ bq,
                            const float* __restrict__ wk, const float* __restrict__ bk,
                            const float* __restrict__ wv, const float* __restrict__ bv) {
    int n = blockIdx.x;          // 0..383
    int c = threadIdx.x;         // 0..255
    float w;
    if (n < 64)       w = wq[c*64 + n];
    else if (n < 128) w = wk[c*64 + (n-64)];
    else              w = wv[c*256 + (n-128)];
    __nv_bfloat16 h, l; bf16_split(w, h, l);
    g_wcbh[n*CC + c] = h;
    g_wcbl[n*CC + c] = l;
    if (c == 0)
        g_bcat[n] = (n < 64) ? bq[n] : (n < 128) ? bk[n-64] : bv[n-128];
}

// ---------------- prep: weight-norm conv weights -----------------------------
__global__ void k_prep_convw(const float* __restrict__ v1, const float* __restrict__ g1,
                             const float* __restrict__ v2, const float* __restrict__ g2) {
    int layer = blockIdx.x >> 8;
    int o = blockIdx.x & 255;
    const float* v = layer ? v2 : v1;
    const float* g = layer ? g2 : g1;
    __nv_bfloat16* wh = layer ? g_w2bh : g_w1bh;
    __nv_bfloat16* wl = layer ? g_w2bl : g_w1bl;
    int tid = threadIdx.x;
    float vv[3];
    float part = 0.f;
#pragma unroll
    for (int k = 0; k < 3; k++) {
        vv[k] = v[((size_t)o*CC + tid)*3 + k];
        part += vv[k]*vv[k];
    }
    __shared__ float sm[256];
    sm[tid] = part; __syncthreads();
    for (int s = 128; s > 0; s >>= 1) {
        if (tid < s) sm[tid] += sm[tid+s];
        __syncthreads();
    }
    float scale = g[o] * rsqrtf(sm[0]);
#pragma unroll
    for (int k = 0; k < 3; k++) {
        float w = scale * vv[k];
        __nv_bfloat16 h, l; bf16_split(w, h, l);
        wh[(size_t)o*CONVK + k*CC + tid] = h;
        wl[(size_t)o*CONVK + k*CC + tid] = l;
    }
}

// ---------------- qkv GEMM (mma): [t][384] = xT @ wcat -----------------------
__global__ void __launch_bounds__(256) k_qkv_mma() {
    extern __shared__ __align__(16) char smem[];
    int m0 = blockIdx.x * 128;
    int n0 = blockIdx.y * 128;
    int tid = threadIdx.x;
    int wid = tid >> 5, lane = tid & 31;
    int warp_m = wid & 3, warp_n = wid >> 2;
    int g = lane >> 3 << 1 | (lane >> 2 & 1); // careful: use standard g
    g = lane >> 2; int tg = lane & 3;
    u32 sbase = smem_u32(smem);
    int lrow = tid >> 1, lhalf = tid & 1;

    float acc[2][8][4];
#pragma unroll
    for (int a = 0; a < 2; a++)
#pragma unroll
        for (int c = 0; c < 8; c++)
#pragma unroll
            for (int d = 0; d < 4; d++) acc[a][c][d] = 0.f;

    auto issue = [&](int cc, int s) {
        size_t ga = (size_t)(m0 + lrow)*CC + cc*32 + lhalf*16;
        size_t gb = (size_t)(n0 + lrow)*CC + cc*32 + lhalf*16;
        u32 d0 = sbase + s*STG + lrow*ROWB + lhalf*32;
        cp16(d0,            g_xth + ga,  true);
        cp16(d0 + 16,       g_xth + ga + 8, true);
        cp16(d0 + MATB,     g_xtl + ga,  true);
        cp16(d0 + MATB+16,  g_xtl + ga + 8, true);
        cp16(d0 + 2*MATB,    g_wcbh + gb, true);
        cp16(d0 + 2*MATB+16, g_wcbh + gb + 8, true);
        cp16(d0 + 3*MATB,    g_wcbl + gb, true);
        cp16(d0 + 3*MATB+16, g_wcbl + gb + 8, true);
    };

    issue(0, 0); CP_COMMIT();
    for (int cc = 0; cc < 8; cc++) {
        int s = cc & 1;
        if (cc < 7) { issue(cc + 1, s ^ 1); CP_COMMIT(); CP_WAIT(1); }
        else CP_WAIT(0);
        __syncthreads();
        const char* Ah = smem + s*STG;
        mma_chunk(Ah, Ah + MATB, Ah + 2*MATB, Ah + 3*MATB, warp_m, warp_n, g, tg, acc);
        __syncthreads();
    }

    int b = m0 >> 10, t0 = m0 & 1023;
#pragma unroll
    for (int mt = 0; mt < 2; mt++) {
        int mr = warp_m*32 + mt*16 + g;
#pragma unroll
        for (int nt = 0; nt < 8; nt++) {
            int n = n0 + warp_n*64 + nt*8 + tg*2;
            float* c = acc[mt][nt];
            float v00 = c[0] + g_bcat[n],   v01 = c[1] + g_bcat[n+1];
            float v10 = c[2] + g_bcat[n],   v11 = c[3] + g_bcat[n+1];
            __nv_bfloat16 h0,l0,h1,l1;
            if (n < 128) {
                __nv_bfloat16* ph = (n < 64) ? g_qh : g_kh;
                __nv_bfloat16* pl = (n < 64) ? g_ql : g_kl;
                int nn = n & 63;
                size_t i_lo = (size_t)(m0 + mr)*64 + nn;
                size_t i_hi = (size_t)(m0 + mr + 8)*64 + nn;
                bf16_split(v00, h0, l0); bf16_split(v01, h1, l1);
                *(__nv_bfloat162*)&ph[i_lo] = __nv_bfloat162(h0, h1);
                *(__nv_bfloat162*)&pl[i_lo] = __nv_bfloat162(l0, l1);
                bf16_split(v10, h0, l0); bf16_split(v11, h1, l1);
                *(__nv_bfloat162*)&ph[i_hi] = __nv_bfloat162(h0, h1);
                *(__nv_bfloat162*)&pl[i_hi] = __nv_bfloat162(l0, l1);
            } else {
                int cch = n - 128;
                int t_lo = t0 + mr, t_hi = t_lo + 8;
                size_t b00 = ((size_t)b*CC + cch)*TT;
                bf16_split(v00, h0, l0);
                g_vth[b00 + t_lo] = h0; g_vtl[b00 + t_lo] = l0;
                bf16_split(v10, h0, l0);
                g_vth[b00 + t_hi] = h0; g_vtl[b00 + t_hi] = l0;
                bf16_split(v01, h1, l1);
                g_vth[b00 + TT + t_lo] = h1; g_vtl[b00 + TT + t_lo] = l1;
                bf16_split(v11, h1, l1);
                g_vth[b00 + TT + t_hi] = h1; g_vtl[b00 + TT + t_hi] = l1;
            }
        }
    }
}

// ---------------- scores GEMM (mma): st[b][j][i] = k.q/8, band only ----------
__global__ void __launch_bounds__(256) k_scores_mma() {
    int i0 = blockIdx.x * 128, j0 = blockIdx.y * 128, b = blockIdx.z;
    if (j0 > i0) return;
    extern __shared__ __align__(16) char smem[];
    int tid = threadIdx.x;
    int wid = tid >> 5, lane = tid & 31;
    int warp_m = wid & 3, warp_n = wid >> 2;
    int g = lane >> 2, tg = lane & 3;
    u32 sbase = smem_u32(smem);
    int lrow = tid >> 1, lhalf = tid & 1;

    float acc[2][8][4];
#pragma unroll
    for (int a = 0; a < 2; a++)
#pragma unroll
        for (int c = 0; c < 8; c++)
#pragma unroll
            for (int d = 0; d < 4; d++) acc[a][c][d] = 0.f;

    const __nv_bfloat16* Ahp = g_kh + (size_t)(b*TT + j0)*64;
    const __nv_bfloat16* Alp = g_kl + (size_t)(b*TT + j0)*64;
    const __nv_bfloat16* Bhp = g_qh + (size_t)(b*TT + i0)*64;
    const __nv_bfloat16* Blp = g_ql + (size_t)(b*TT + i0)*64;

    auto issue = [&](int cc, int s) {
        size_t ga = (size_t)lrow*64 + cc*32 + lhalf*16;
        u32 d0 = sbase + s*STG + lrow*ROWB + lhalf*32;
        cp16(d0,            Ahp + ga, true);
        cp16(d0 + 16,       Ahp + ga + 8, true);
        cp16(d0 + MATB,     Alp + ga, true);
        cp16(d0 + MATB+16,  Alp + ga + 8, true);
        cp16(d0 + 2*MATB,    Bhp + ga, true);
        cp16(d0 + 2*MATB+16, Bhp + ga + 8, true);
        cp16(d0 + 3*MATB,    Blp + ga, true);
        cp16(d0 + 3*MATB+16, Blp + ga + 8, true);
    };

    issue(0, 0); CP_COMMIT();
    for (int cc = 0; cc < 2; cc++) {
        int s = cc & 1;
        if (cc < 1) { issue(1, 1); CP_COMMIT(); CP_WAIT(1); }
        else CP_WAIT(0);
        __syncthreads();
        const char* Ah = smem + s*STG;
        mma_chunk(Ah, Ah + MATB, Ah + 2*MATB, Ah + 3*MATB, warp_m, warp_n, g, tg, acc);
        __syncthreads();
    }

    size_t base = (size_t)b*TT*TT;
#pragma unroll
    for (int mt = 0; mt < 2; mt++) {
        int j_lo = j0 + warp_m*32 + mt*16 + g;
#pragma unroll
        for (int nt = 0; nt < 8; nt++) {
            int i = i0 + warp_n*64 + nt*8 + tg*2;
            float* c = acc[mt][nt];
            *(float2*)&g_st[base + (size_t)j_lo*TT + i] =
                make_float2(c[0]*0.125f, c[1]*0.125f);
            *(float2*)&g_st[base + (size_t)(j_lo+8)*TT + i] =
                make_float2(c[2]*0.125f, c[3]*0.125f);
        }
    }
}

// ---------------- per-(b,j) softmax stats over i in [j, T) -------------------
__global__ void k_stats() {
    int row = blockIdx.x;
    int b = row >> 10, j = row & 1023;
    const float* p = g_st + (size_t)b*TT*TT + (size_t)j*TT;
    int tid = threadIdx.x;
    __shared__ float sm[128];
    float mx = -1e30f;
    for (int i = j + tid; i < TT; i += 128) mx = fmaxf(mx, p[i]);
    sm[tid] = mx; __syncthreads();
    for (int s = 64; s > 0; s >>= 1) {
        if (tid < s) sm[tid] = fmaxf(sm[tid], sm[tid+s]);
        __syncthreads();
    }
    mx = sm[0]; __syncthreads();
    float sum = 0.f;
    for (int i = j + tid; i < TT; i += 128) sum += __expf(p[i] - mx);
    sm[tid] = sum; __syncthreads();
    for (int s = 64; s > 0; s >>= 1) {
        if (tid < s) sm[tid] += sm[tid+s];
        __syncthreads();
    }
    if (tid == 0) { g_m[row] = mx; g_rz[row] = 1.f / sm[0]; }
}

// ---------------- attn transpose-split: st[j][i] -> ath/atl[i][j] ------------
__global__ void __launch_bounds__(256) k_attn_t() {
    int i0 = blockIdx.x * 64, j0 = blockIdx.y * 64, b = blockIdx.z;
    if (j0 > i0) return;
    __shared__ float sm[64][65];
    int tid = threadIdx.x;
    int il = tid & 63, jg = tid >> 6;
    size_t base = (size_t)b*TT*TT;
#pragma unroll 4
    for (int r = 0; r < 16; r++) {
        int j = j0 + jg*16 + r;
        float mj = g_m[b*TT + j];
        float rz = g_rz[b*TT + j];
        int i = i0 + il;
        float a = 0.f;
        if (i >= j) a = __expf(g_st[base + (size_t)j*TT + i] - mj) * rz;
        sm[jg*16 + r][il] = a;
    }
    __syncthreads();
    int jl = tid & 63, ig = tid >> 6;
#pragma unroll 4
    for (int r = 0; r < 16; r++) {
        int i_local = ig*16 + r;
        float a = sm[jl][i_local];
        __nv_bfloat16 h, l; bf16_split(a, h, l);
        size_t idx = ((size_t)b*TT + i0 + i_local)*TT + j0 + jl;
        g_ath[idx] = h;
        g_atl[idx] = l;
    }
}

// ---------------- rowsum[b,i] = sum_j attn[i][j] -----------------------------
__global__ void k_rowsum() {
    int i0 = blockIdx.x * 64, b = blockIdx.y;
    int tid = threadIdx.x;
    int ir = tid >> 2, jr = tid & 3;
    int i = i0 + ir;
    size_t rb = ((size_t)b*TT + i)*TT;
    int jmax = i0 + 64;
    float s = 0.f;
    for (int j = jr*2; j < jmax; j += 8) {
        float2 h = __bfloat1622float2(*(const __nv_bfloat162*)&g_ath[rb + j]);
        float2 l = __bfloat1622float2(*(const __nv_bfloat162*)&g_atl[rb + j]);
        s += h.x + h.y + l.x + l.y;
    }
    s += __shfl_xor_sync(0xffffffffu, s, 1);
    s += __shfl_xor_sync(0xffffffffu, s, 2);
    if (jr == 0) g_rowsum[b*TT + i] = s;
}

// ---------------- weight_x = softmax_t(rowsum) -------------------------------
__global__ void k_wx() {
    int b = blockIdx.x, tid = threadIdx.x;
    __shared__ float sm[256];
    float v[4], e[4];
    float mx = -1e30f;
#pragma unroll
    for (int r = 0; r < 4; r++) {
        v[r] = g_rowsum[b*TT + tid + r*256];
        mx = fmaxf(mx, v[r]);
    }
    sm[tid] = mx; __syncthreads();
    for (int s = 128; s > 0; s >>= 1) {
        if (tid < s) sm[tid] = fmaxf(sm[tid], sm[tid+s]);
        __syncthreads();
    }
    mx = sm[0]; __syncthreads();
    float sum = 0.f;
#pragma unroll
    for (int r = 0; r < 4; r++) { e[r] = __expf(v[r] - mx); sum += e[r]; }
    sm[tid] = sum; __syncthreads();
    for (int s = 128; s > 0; s >>= 1) {
        if (tid < s) sm[tid] += sm[tid+s];
        __syncthreads();
    }
    float rz = 1.f / sm[0];
#pragma unroll
    for (int r = 0; r < 4; r++) g_wx[b*TT + tid + r*256] = e[r] * rz;
}

// ---------------- av GEMM (mma): h1[i][c] = attn @ v, banded K ---------------
__global__ void __launch_bounds__(256) k_av_mma() {
    extern __shared__ __align__(16) char smem[];
    int m0 = blockIdx.x * 128;
    int n0 = blockIdx.y * 128;
    int b = m0 >> 10, t0 = m0 & 1023;
    int tid = threadIdx.x;
    int wid = tid >> 5, lane = tid & 31;
    int warp_m = wid & 3, warp_n = wid >> 2;
    int g = lane >> 2, tg = lane & 3;
    u32 sbase = smem_u32(smem);
    int lrow = tid >> 1, lhalf = tid & 1;

    float acc[2][8][4];
#pragma unroll
    for (int a = 0; a < 2; a++)
#pragma unroll
        for (int c = 0; c < 8; c++)
#pragma unroll
            for (int d = 0; d < 4; d++) acc[a][c][d] = 0.f;

    const __nv_bfloat16* Ahp = g_ath + ((size_t)b*TT + t0)*TT;
    const __nv_bfloat16* Alp = g_atl + ((size_t)b*TT + t0)*TT;
    const __nv_bfloat16* Bhp = g_vth + ((size_t)b*CC + n0)*TT;
    const __nv_bfloat16* Blp = g_vtl + ((size_t)b*CC + n0)*TT;
    int nch = (t0 + 128) >> 5;

    auto issue = [&](int cc, int s) {
        size_t ga = (size_t)lrow*TT + cc*32 + lhalf*16;
        u32 d0 = sbase + s*STG + lrow*ROWB + lhalf*32;
        cp16(d0,            Ahp + ga, true);
        cp16(d0 + 16,       Ahp + ga + 8, true);
        cp16(d0 + MATB,     Alp + ga, true);
        cp16(d0 + MATB+16,  Alp + ga + 8, true);
        cp16(d0 + 2*MATB,    Bhp + ga, true);
        cp16(d0 + 2*MATB+16, Bhp + ga + 8, true);
        cp16(d0 + 3*MATB,    Blp + ga, true);
        cp16(d0 + 3*MATB+16, Blp + ga + 8, true);
    };

    issue(0, 0); CP_COMMIT();
    for (int cc = 0; cc < nch; cc++) {
        int s = cc & 1;
        if (cc < nch - 1) { issue(cc + 1, s ^ 1); CP_COMMIT(); CP_WAIT(1); }
        else CP_WAIT(0);
        __syncthreads();
        const char* Ah = smem + s*STG;
        mma_chunk(Ah, Ah + MATB, Ah + 2*MATB, Ah + 3*MATB, warp_m, warp_n, g, tg, acc);
        __syncthreads();
    }

#pragma unroll
    for (int mt = 0; mt < 2; mt++) {
        int m_lo = m0 + warp_m*32 + mt*16 + g;
#pragma unroll
        for (int nt = 0; nt < 8; nt++) {
            int n = n0 + warp_n*64 + nt*8 + tg*2;
            float* c = acc[mt][nt];
            __nv_bfloat16 h0,l0,h1,l1;
            size_t i_lo = (size_t)m_lo*CC + n;
            size_t i_hi = (size_t)(m_lo+8)*CC + n;
            bf16_split(c[0], h0, l0); bf16_split(c[1], h1, l1);
            *(__nv_bfloat162*)&g_h1h[i_lo] = __nv_bfloat162(h0, h1);
            *(__nv_bfloat162*)&g_h1l[i_lo] = __nv_bfloat162(l0, l1);
            bf16_split(c[2], h0, l0); bf16_split(c[3], h1, l1);
            *(__nv_bfloat162*)&g_h1h[i_hi] = __nv_bfloat162(h0, h1);
            *(__nv_bfloat162*)&g_h1l[i_hi] = __nv_bfloat162(l0, l1);
        }
    }
}

// ---------------- conv GEMM (mma), unchanged from round 4 --------------------
__global__ void __launch_bounds__(256) k_conv_mma(int mode,
                                                  const float* __restrict__ bias,
                                                  const float* __restrict__ x,
                                                  float* __restrict__ outp) {
    extern __shared__ __align__(16) char smem[];
    const __nv_bfloat16* Ahp = mode ? g_h2h  : g_h1h;
    const __nv_bfloat16* Alp = mode ? g_h2l  : g_h1l;
    const __nv_bfloat16* Bhp = mode ? g_w2bh : g_w1bh;
    const __nv_bfloat16* Blp = mode ? g_w2bl : g_w1bl;

    int m0 = blockIdx.x * 128;
    int n0 = blockIdx.y * 128;
    int b = m0 >> 10, t0 = m0 & 1023;
    int tid = threadIdx.x;
    int wid = tid >> 5, lane = tid & 31;
    int warp_m = wid & 3, warp_n = wid >> 2;
    int g = lane >> 2, tg = lane & 3;
    u32 sbase = smem_u32(smem);
    int lrow = tid >> 1, lhalf = tid & 1;

    float acc[2][8][4];
#pragma unroll
    for (int a = 0; a < 2; a++)
#pragma unroll
        for (int c = 0; c < 8; c++)
#pragma unroll
            for (int d = 0; d < 4; d++) acc[a][c][d] = 0.f;

    auto issue = [&](int cc, int s) {
        int koff = cc >> 3, i0c = (cc & 7) * 32;
        int t = t0 + lrow + koff - 2;
        bool ok = (t >= 0);
        size_t ga = (size_t)(b*TT + t)*CC + i0c + lhalf*16;
        size_t gb = (size_t)(n0 + lrow)*CONVK + cc*32 + lhalf*16;
        u32 d0 = sbase + s*STG + lrow*ROWB + lhalf*32;
        cp16(d0,            Ahp + ga,     ok);
        cp16(d0 + 16,       Ahp + ga + 8, ok);
        cp16(d0 + MATB,     Alp + ga,     ok);
        cp16(d0 + MATB+16,  Alp + ga + 8, ok);
        cp16(d0 + 2*MATB,    Bhp + gb,     true);
        cp16(d0 + 2*MATB+16, Bhp + gb + 8, true);
        cp16(d0 + 3*MATB,    Blp + gb,     true);
        cp16(d0 + 3*MATB+16, Blp + gb + 8, true);
    };

    issue(0, 0); CP_COMMIT();
    for (int cc = 0; cc < 24; cc++) {
        int s = cc & 1;
        if (cc < 23) { issue(cc + 1, s ^ 1); CP_COMMIT(); CP_WAIT(1); }
        else CP_WAIT(0);
        __syncthreads();
        const char* Ah = smem + s*STG;
        mma_chunk(Ah, Ah + MATB, Ah + 2*MATB, Ah + 3*MATB, warp_m, warp_n, g, tg, acc);
        __syncthreads();
    }

#pragma unroll
    for (int mt = 0; mt < 2; mt++) {
        int t_lo = t0 + warp_m*32 + mt*16 + g;
        int t_hi = t_lo + 8;
        if (mode == 0) {
#pragma unroll
            for (int nt = 0; nt < 8; nt++) {
                int n = n0 + warp_n*64 + nt*8 + tg*2;
                float b0 = bias[n], b1 = bias[n+1];
                float* c = acc[mt][nt];
                float v0 = fmaxf(c[0] + b0, 0.f);
                float v1 = fmaxf(c[1] + b1, 0.f);
                float v2 = fmaxf(c[2] + b0, 0.f);
                float v3 = fmaxf(c[3] + b1, 0.f);
                __nv_bfloat16 h0,l0,h1,l1;
                bf16_split(v0, h0, l0); bf16_split(v1, h1, l1);
                size_t i_lo = (size_t)(b*TT + t_lo)*CC + n;
                *(__nv_bfloat162*)&g_h2h[i_lo] = __nv_bfloat162(h0, h1);
                *(__nv_bfloat162*)&g_h2l[i_lo] = __nv_bfloat162(l0, l1);
                bf16_split(v2, h0, l0); bf16_split(v3, h1, l1);
                size_t i_hi = (size_t)(b*TT + t_hi)*CC + n;
                *(__nv_bfloat162*)&g_h2h[i_hi] = __nv_bfloat162(h0, h1);
                *(__nv_bfloat162*)&g_h2l[i_hi] = __nv_bfloat162(l0, l1);
            }
        } else {
            float w_lo = 1.f + g_wx[b*TT + t_lo];
            float w_hi = 1.f + g_wx[b*TT + t_hi];
#pragma unroll
            for (int nt = 0; nt < 8; nt++) {
                int n = n0 + warp_n*64 + nt*8 + tg*2;
                float b0 = bias[n], b1 = bias[n+1];
                float* c = acc[mt][nt];
                size_t o00 = ((size_t)b*CC + n)*TT + t_lo;
                size_t o10 = o00 + TT;
                size_t o01 = o00 + 8;
                size_t o11 = o10 + 8;
                outp[o00] = fmaxf(fmaxf(c[0] + b0, 0.f) + x[o00]*w_lo, 0.f);
                outp[o10] = fmaxf(fmaxf(c[1] + b1, 0.f) + x[o10]*w_lo, 0.f);
                outp[o01] = fmaxf(fmaxf(c[2] + b0, 0.f) + x[o01]*w_hi, 0.f);
                outp[o11] = fmaxf(fmaxf(c[3] + b1, 0.f) + x[o11]*w_hi, 0.f);
            }
        }
    }
}

// ---------------- launch ------------------------------------------------------
extern "C" void kernel_launch(void* const* d_in, const int* in_sizes, int n_in,
                              void* d_out, int out_size) {
    const float* x  = (const float*)d_in[0];
    const float* wq = (const float*)d_in[1];
    const float* bq = (const float*)d_in[2];
    const float* wk = (const float*)d_in[3];
    const float* bk = (const float*)d_in[4];
    const float* wv = (const float*)d_in[5];
    const float* bv = (const float*)d_in[6];
    const float* v1 = (const float*)d_in[7];
    const float* g1 = (const float*)d_in[8];
    const float* b1 = (const float*)d_in[9];
    const float* v2 = (const float*)d_in[10];
    const float* g2 = (const float*)d_in[11];
    const float* b2 = (const float*)d_in[12];
    float* out = (float*)d_out;

    static int smset = 0;
    if (!smset) {
        cudaFuncSetAttribute(k_qkv_mma,    cudaFuncAttributeMaxDynamicSharedMemorySize, MMA_SMEM);
        cudaFuncSetAttribute(k_scores_mma, cudaFuncAttributeMaxDynamicSharedMemorySize, MMA_SMEM);
        cudaFuncSetAttribute(k_av_mma,     cudaFuncAttributeMaxDynamicSharedMemorySize, MMA_SMEM);
        cudaFuncSetAttribute(k_conv_mma,   cudaFuncAttributeMaxDynamicSharedMemorySize, MMA_SMEM);
        smset = 1;
    }

    k_prep_xt<<<dim3(TT/32, CC/32, BB), 256>>>(x);
    k_prep_wcat<<<QKVW, 256>>>(wq, bq, wk, bk, wv, bv);
    k_prep_convw<<<512, 256>>>(v1, g1, v2, g2);
    k_qkv_mma<<<dim3(MT/128, 3), 256, MMA_SMEM>>>();
    k_scores_mma<<<dim3(8, 8, BB), 256, MMA_SMEM>>>();
    k_stats<<<MT, 128>>>();
    k_attn_t<<<dim3(16, 16, BB), 256>>>();
    k_rowsum<<<dim3(16, BB), 256>>>();
    k_wx<<<BB, 256>>>();
    k_av_mma<<<dim3(MT/128, CC/128), 256, MMA_SMEM>>>();
    k_conv_mma<<<dim3(MT/128, CC/128), 256, MMA_SMEM>>>(0, b1, x, out);
    k_conv_mma<<<dim3(MT/128, CC/128), 256, MMA_SMEM>>>(1, b2, x, out);
}

// round 6
// speedup vs baseline: 2.6958x; 1.1087x over previous
#include <cuda_runtime.h>
#include <cuda_bf16.h>
#include <cstdint>

#define BB 32
#define CC 256
#define TT 1024
#define QKVW 384
#define MT (BB*TT)
#define CONVK 768

typedef uint32_t u32;

// ---------------- scratch (device globals; zero-initialized BSS) -------------
__device__ float g_bcat[QKVW];
__device__ float g_st[(size_t)BB*TT*TT];     // scores [b][j][i]
__device__ float g_m[MT];
__device__ float g_rz[MT];
__device__ float g_rsp[(size_t)MT*16];       // rowsum partials per j-tile
__device__ float g_rowsum[MT];
__device__ float g_wx[MT];
// bf16 split operands
__device__ __align__(16) __nv_bfloat16 g_xth[(size_t)MT*CC];  // x^T [t][c]
__device__ __align__(16) __nv_bfloat16 g_xtl[(size_t)MT*CC];
__device__ __align__(16) __nv_bfloat16 g_wcbh[QKVW*CC];       // wcat^T [n][c]
__device__ __align__(16) __nv_bfloat16 g_wcbl[QKVW*CC];
__device__ __align__(16) __nv_bfloat16 g_qh[(size_t)MT*64];
__device__ __align__(16) __nv_bfloat16 g_ql[(size_t)MT*64];
__device__ __align__(16) __nv_bfloat16 g_kh[(size_t)MT*64];
__device__ __align__(16) __nv_bfloat16 g_kl[(size_t)MT*64];
__device__ __align__(16) __nv_bfloat16 g_vth[(size_t)BB*CC*TT]; // v^T [b][c][t]
__device__ __align__(16) __nv_bfloat16 g_vtl[(size_t)BB*CC*TT];
__device__ __align__(16) __nv_bfloat16 g_ath[(size_t)BB*TT*TT]; // attn [b][i][j]
__device__ __align__(16) __nv_bfloat16 g_atl[(size_t)BB*TT*TT]; // unwritten = 0
__device__ __align__(16) __nv_bfloat16 g_h1h[(size_t)MT*CC];
__device__ __align__(16) __nv_bfloat16 g_h1l[(size_t)MT*CC];
__device__ __align__(16) __nv_bfloat16 g_h2h[(size_t)MT*CC];
__device__ __align__(16) __nv_bfloat16 g_h2l[(size_t)MT*CC];
__device__ __align__(16) __nv_bfloat16 g_w1bh[CC*CONVK];
__device__ __align__(16) __nv_bfloat16 g_w1bl[CC*CONVK];
__device__ __align__(16) __nv_bfloat16 g_w2bh[CC*CONVK];
__device__ __align__(16) __nv_bfloat16 g_w2bl[CC*CONVK];

// ---------------- helpers ----------------------------------------------------
__device__ __forceinline__ u32 smem_u32(const void* p) {
    u32 a;
    asm("{ .reg .u64 t; cvta.to.shared.u64 t, %1; cvt.u32.u64 %0, t; }"
        : "=r"(a) : "l"(p));
    return a;
}
__device__ __forceinline__ void cp16(u32 dst, const void* src, bool ok) {
    int sz = ok ? 16 : 0;
    asm volatile("cp.async.cg.shared.global [%0], [%1], 16, %2;"
                 :: "r"(dst), "l"(src), "r"(sz) : "memory");
}
#define CP_COMMIT() asm volatile("cp.async.commit_group;" ::: "memory")
#define CP_WAIT1()  asm volatile("cp.async.wait_group 1;" ::: "memory")
#define CP_WAIT0()  asm volatile("cp.async.wait_group 0;" ::: "memory")

__device__ __forceinline__ void mma16816(float c[4], const u32 a[4], const u32 b[2]) {
    asm volatile(
        "mma.sync.aligned.m16n8k16.row.col.f32.bf16.bf16.f32 "
        "{%0,%1,%2,%3}, {%4,%5,%6,%7}, {%8,%9}, {%0,%1,%2,%3};"
        : "+f"(c[0]), "+f"(c[1]), "+f"(c[2]), "+f"(c[3])
        : "r"(a[0]), "r"(a[1]), "r"(a[2]), "r"(a[3]), "r"(b[0]), "r"(b[1]));
}
__device__ __forceinline__ void bf16_split(float v, __nv_bfloat16& h, __nv_bfloat16& l) {
    h = __float2bfloat16(v);
    l = __float2bfloat16(v - __bfloat162float(h));
}

// ---- stage geometry: A 128 rows x 32K (h,l) + B 64 rows x 32K (h,l) ---------
#define ROWB 80
#define A_MATB (128*ROWB)      // 10240
#define B_MATB (64*ROWB)       // 5120
#define STG (2*A_MATB + 2*B_MATB)   // 30720
#define MMA_SMEM (3*STG)       // 92160 -> 2 CTAs/SM

// one K=32 chunk: warp tile 32(M) x 32(N): mt 2x16, nt 4x8
__device__ __forceinline__ void mma_chunk4(const char* base,
                                           int warp_m, int warp_n, int g, int tg,
                                           float acc[2][4][4]) {
    const char* Ah = base;
    const char* Al = base + A_MATB;
    const char* Bh = base + 2*A_MATB;
    const char* Bl = base + 2*A_MATB + B_MATB;
#pragma unroll
    for (int ks = 0; ks < 2; ks++) {
        u32 ah[2][4], al[2][4];
#pragma unroll
        for (int mt = 0; mt < 2; mt++) {
            int o0 = (warp_m*32 + mt*16 + g)*ROWB + ks*32 + tg*4;
            ah[mt][0] = *(const u32*)(Ah + o0);
            ah[mt][1] = *(const u32*)(Ah + o0 + 8*ROWB);
            ah[mt][2] = *(const u32*)(Ah + o0 + 16);
            ah[mt][3] = *(const u32*)(Ah + o0 + 8*ROWB + 16);
            al[mt][0] = *(const u32*)(Al + o0);
            al[mt][1] = *(const u32*)(Al + o0 + 8*ROWB);
            al[mt][2] = *(const u32*)(Al + o0 + 16);
            al[mt][3] = *(const u32*)(Al + o0 + 8*ROWB + 16);
        }
        u32 bh[4][2], bl[4][2];
#pragma unroll
        for (int nt = 0; nt < 4; nt++) {
            int o0 = (warp_n*32 + nt*8 + g)*ROWB + ks*32 + tg*4;
            bh[nt][0] = *(const u32*)(Bh + o0);
            bh[nt][1] = *(const u32*)(Bh + o0 + 16);
            bl[nt][0] = *(const u32*)(Bl + o0);
            bl[nt][1] = *(const u32*)(Bl + o0 + 16);
        }
#pragma unroll
        for (int mt = 0; mt < 2; mt++)
#pragma unroll
            for (int nt = 0; nt < 4; nt++) {
                mma16816(acc[mt][nt], ah[mt], bh[nt]);
                mma16816(acc[mt][nt], ah[mt], bl[nt]);
                mma16816(acc[mt][nt], al[mt], bh[nt]);
            }
    }
}

// shared mainloop macro: ISSUE(cc, stage_u32_base) must cp all 4 matrices
#define MMA_MAINLOOP(NCH)                                                     \
    { ISSUE(0, sbase); } CP_COMMIT();                                         \
    { ISSUE(1, sbase + STG); } CP_COMMIT();                                   \
    for (int cc = 0; cc < (NCH); cc++) {                                      \
        int s = cc % 3;                                                       \
        if (cc + 1 < (NCH)) { CP_WAIT1(); } else { CP_WAIT0(); }              \
        __syncthreads();                                                      \
        mma_chunk4(smem + s*STG, warp_m, warp_n, g, tg, acc);                 \
        if (cc + 2 < (NCH)) {                                                 \
            int s2 = (s + 2) % 3;                                             \
            ISSUE(cc + 2, sbase + s2*STG);                                    \
            CP_COMMIT();                                                      \
        }                                                                     \
    }

// ---------------- prep: transpose-split x ------------------------------------
__global__ void k_prep_xt(const float* __restrict__ x) {
    __shared__ float sm[32][33];
    int t0 = blockIdx.x * 32, c0 = blockIdx.y * 32, b = blockIdx.z;
    int lane = threadIdx.x & 31, grp = threadIdx.x >> 5;
#pragma unroll
    for (int r = 0; r < 4; r++) {
        int c = grp + r*8;
        sm[c][lane] = x[((size_t)b*CC + c0 + c)*TT + t0 + lane];
    }
    __syncthreads();
#pragma unroll
    for (int r = 0; r < 4; r++) {
        int t = grp + r*8;
        float v = sm[lane][t];
        __nv_bfloat16 h, l; bf16_split(v, h, l);
        size_t idx = (size_t)(b*TT + t0 + t)*CC + c0 + lane;
        g_xth[idx] = h; g_xtl[idx] = l;
    }
}

// ---------------- prep: wcat^T split + bcat ----------------------------------
__global__ void k_prep_wcat(const float* __restrict__ wq, const float* __restrict__ bq,
                            const float* __restrict__ wk, const float* __restrict__ bk,
                            const float* __restrict__ wv, const float* __restrict__ bv) {
    int n = blockIdx.x;
    int c = threadIdx.x;
    float w;
    if (n < 64)       w = wq[c*64 + n];
    else if (n < 128) w = wk[c*64 + (n-64)];
    else              w = wv[c*256 + (n-128)];
    __nv_bfloat16 h, l; bf16_split(w, h, l);
    g_wcbh[n*CC + c] = h;
    g_wcbl[n*CC + c] = l;
    if (c == 0)
        g_bcat[n] = (n < 64) ? bq[n] : (n < 128) ? bk[n-64] : bv[n-128];
}

// ---------------- prep: weight-norm conv weights -----------------------------
__global__ void k_prep_convw(const float* __restrict__ v1, const float* __restrict__ g1,
                             const float* __restrict__ v2, const float* __restrict__ g2) {
    int layer = blockIdx.x >> 8;
    int o = blockIdx.x & 255;
    const float* v = layer ? v2 : v1;
    const float* g = layer ? g2 : g1;
    __nv_bfloat16* wh = layer ? g_w2bh : g_w1bh;
    __nv_bfloat16* wl = layer ? g_w2bl : g_w1bl;
    int tid = threadIdx.x;
    float vv[3];
    float part = 0.f;
#pragma unroll
    for (int k = 0; k < 3; k++) {
        vv[k] = v[((size_t)o*CC + tid)*3 + k];
        part += vv[k]*vv[k];
    }
    __shared__ float sm[256];
    sm[tid] = part; __syncthreads();
    for (int s = 128; s > 0; s >>= 1) {
        if (tid < s) sm[tid] += sm[tid+s];
        __syncthreads();
    }
    float scale = g[o] * rsqrtf(sm[0]);
#pragma unroll
    for (int k = 0; k < 3; k++) {
        float w = scale * vv[k];
        __nv_bfloat16 h, l; bf16_split(w, h, l);
        wh[(size_t)o*CONVK + k*CC + tid] = h;
        wl[(size_t)o*CONVK + k*CC + tid] = l;
    }
}

// ---------------- qkv GEMM -----------------------------------------------------
__global__ void __launch_bounds__(256, 2) k_qkv_mma() {
    extern __shared__ __align__(16) char smem[];
    int m0 = blockIdx.x * 128;
    int n0 = blockIdx.y * 64;
    int tid = threadIdx.x;
    int wid = tid >> 5, lane = tid & 31;
    int warp_m = wid & 3, warp_n = wid >> 2;
    int g = lane >> 2, tg = lane & 3;
    u32 sbase = smem_u32(smem);
    int arow = tid >> 1, ahalf = tid & 1;
    int brow = tid >> 2, bq4 = tid & 3;

    float acc[2][4][4];
#pragma unroll
    for (int a = 0; a < 2; a++)
#pragma unroll
        for (int c = 0; c < 4; c++)
#pragma unroll
            for (int d = 0; d < 4; d++) acc[a][c][d] = 0.f;

#define ISSUE(cc, st) do {                                                    \
        size_t ga = (size_t)(m0 + arow)*CC + (cc)*32 + ahalf*16;              \
        u32 da = (st) + arow*ROWB + ahalf*32;                                 \
        cp16(da,              g_xth + ga,     true);                          \
        cp16(da + 16,         g_xth + ga + 8, true);                          \
        cp16(da + A_MATB,     g_xtl + ga,     true);                          \
        cp16(da + A_MATB+16,  g_xtl + ga + 8, true);                          \
        size_t gb = (size_t)(n0 + brow)*CC + (cc)*32 + bq4*8;                 \
        u32 db = (st) + 2*A_MATB + brow*ROWB + bq4*16;                        \
        cp16(db,          g_wcbh + gb, true);                                 \
        cp16(db + B_MATB, g_wcbl + gb, true);                                 \
    } while (0)

    MMA_MAINLOOP(8)
#undef ISSUE

    int b = m0 >> 10, t0 = m0 & 1023;
#pragma unroll
    for (int mt = 0; mt < 2; mt++) {
        int mr = warp_m*32 + mt*16 + g;
#pragma unroll
        for (int nt = 0; nt < 4; nt++) {
            int n = n0 + warp_n*32 + nt*8 + tg*2;
            float* c = acc[mt][nt];
            float v00 = c[0] + g_bcat[n],   v01 = c[1] + g_bcat[n+1];
            float v10 = c[2] + g_bcat[n],   v11 = c[3] + g_bcat[n+1];
            __nv_bfloat16 h0,l0,h1,l1;
            if (n < 128) {
                __nv_bfloat16* ph = (n < 64) ? g_qh : g_kh;
                __nv_bfloat16* pl = (n < 64) ? g_ql : g_kl;
                int nn = n & 63;
                size_t i_lo = (size_t)(m0 + mr)*64 + nn;
                size_t i_hi = (size_t)(m0 + mr + 8)*64 + nn;
                bf16_split(v00, h0, l0); bf16_split(v01, h1, l1);
                *(__nv_bfloat162*)&ph[i_lo] = __nv_bfloat162(h0, h1);
                *(__nv_bfloat162*)&pl[i_lo] = __nv_bfloat162(l0, l1);
                bf16_split(v10, h0, l0); bf16_split(v11, h1, l1);
                *(__nv_bfloat162*)&ph[i_hi] = __nv_bfloat162(h0, h1);
                *(__nv_bfloat162*)&pl[i_hi] = __nv_bfloat162(l0, l1);
            } else {
                int cch = n - 128;
                int t_lo = t0 + mr, t_hi = t_lo + 8;
                size_t b00 = ((size_t)b*CC + cch)*TT;
                bf16_split(v00, h0, l0);
                g_vth[b00 + t_lo] = h0; g_vtl[b00 + t_lo] = l0;
                bf16_split(v10, h0, l0);
                g_vth[b00 + t_hi] = h0; g_vtl[b00 + t_hi] = l0;
                bf16_split(v01, h1, l1);
                g_vth[b00 + TT + t_lo] = h1; g_vtl[b00 + TT + t_lo] = l1;
                bf16_split(v11, h1, l1);
                g_vth[b00 + TT + t_hi] = h1; g_vtl[b00 + TT + t_hi] = l1;
            }
        }
    }
}

// ---------------- scores GEMM: st[b][j][i], band tiles only ------------------
__global__ void __launch_bounds__(256, 2) k_scores_mma() {
    int i0 = blockIdx.x * 64, j0 = blockIdx.y * 128, b = blockIdx.z;
    if (j0 > i0 + 63) return;
    extern __shared__ __align__(16) char smem[];
    int tid = threadIdx.x;
    int wid = tid >> 5, lane = tid & 31;
    int warp_m = wid & 3, warp_n = wid >> 2;
    int g = lane >> 2, tg = lane & 3;
    u32 sbase = smem_u32(smem);
    int arow = tid >> 1, ahalf = tid & 1;
    int brow = tid >> 2, bq4 = tid & 3;

    float acc[2][4][4];
#pragma unroll
    for (int a = 0; a < 2; a++)
#pragma unroll
        for (int c = 0; c < 4; c++)
#pragma unroll
            for (int d = 0; d < 4; d++) acc[a][c][d] = 0.f;

    const __nv_bfloat16* Ahp = g_kh + (size_t)(b*TT + j0)*64;
    const __nv_bfloat16* Alp = g_kl + (size_t)(b*TT + j0)*64;
    const __nv_bfloat16* Bhp = g_qh + (size_t)(b*TT + i0)*64;
    const __nv_bfloat16* Blp = g_ql + (size_t)(b*TT + i0)*64;

#define ISSUE(cc, st) do {                                                    \
        size_t ga = (size_t)arow*64 + (cc)*32 + ahalf*16;                     \
        u32 da = (st) + arow*ROWB + ahalf*32;                                 \
        cp16(da,              Ahp + ga,     true);                            \
        cp16(da + 16,         Ahp + ga + 8, true);                            \
        cp16(da + A_MATB,     Alp + ga,     true);                            \
        cp16(da + A_MATB+16,  Alp + ga + 8, true);                            \
        size_t gb = (size_t)brow*64 + (cc)*32 + bq4*8;                        \
        u32 db = (st) + 2*A_MATB + brow*ROWB + bq4*16;                        \
        cp16(db,          Bhp + gb, true);                                    \
        cp16(db + B_MATB, Blp + gb, true);                                    \
    } while (0)

    MMA_MAINLOOP(2)
#undef ISSUE

    size_t base = (size_t)b*TT*TT;
#pragma unroll
    for (int mt = 0; mt < 2; mt++) {
        int j_lo = j0 + warp_m*32 + mt*16 + g;
#pragma unroll
        for (int nt = 0; nt < 4; nt++) {
            int i = i0 + warp_n*32 + nt*8 + tg*2;
            float* c = acc[mt][nt];
            *(float2*)&g_st[base + (size_t)j_lo*TT + i] =
                make_float2(c[0]*0.125f, c[1]*0.125f);
            *(float2*)&g_st[base + (size_t)(j_lo+8)*TT + i] =
                make_float2(c[2]*0.125f, c[3]*0.125f);
        }
    }
}

// ---------------- per-(b,j) softmax stats over i in [j, T) -------------------
__global__ void k_stats() {
    int row = blockIdx.x;
    int b = row >> 10, j = row & 1023;
    const float* p = g_st + (size_t)b*TT*TT + (size_t)j*TT;
    int tid = threadIdx.x;
    __shared__ float sm[128];
    float mx = -1e30f;
    for (int i = j + tid; i < TT; i += 128) mx = fmaxf(mx, p[i]);
    sm[tid] = mx; __syncthreads();
    for (int s = 64; s > 0; s >>= 1) {
        if (tid < s) sm[tid] = fmaxf(sm[tid], sm[tid+s]);
        __syncthreads();
    }
    mx = sm[0]; __syncthreads();
    float sum = 0.f;
    for (int i = j + tid; i < TT; i += 128) sum += __expf(p[i] - mx);
    sm[tid] = sum; __syncthreads();
    for (int s = 64; s > 0; s >>= 1) {
        if (tid < s) sm[tid] += sm[tid+s];
        __syncthreads();
    }
    if (tid == 0) { g_m[row] = mx; g_rz[row] = 1.f / sm[0]; }
}

// ------- attn transpose-split + fused rowsum partials ------------------------
__global__ void __launch_bounds__(256) k_attn_t() {
    int i0 = blockIdx.x * 64, j0 = blockIdx.y * 64, b = blockIdx.z;
    if (j0 > i0) return;
    __shared__ float sm[64][65];
    __shared__ float s2[4][64];
    int tid = threadIdx.x;
    int il = tid & 63, jg = tid >> 6;
    size_t base = (size_t)b*TT*TT;
    float part = 0.f;
#pragma unroll 4
    for (int r = 0; r < 16; r++) {
        int j = j0 + jg*16 + r;
        float mj = g_m[b*TT + j];
        float rz = g_rz[b*TT + j];
        int i = i0 + il;
        float a = 0.f;
        if (i >= j) a = __expf(g_st[base + (size_t)j*TT + i] - mj) * rz;
        sm[jg*16 + r][il] = a;
        part += a;
    }
    s2[jg][il] = part;
    __syncthreads();
    int jl = tid & 63, ig = tid >> 6;
#pragma unroll 4
    for (int r = 0; r < 16; r++) {
        int i_local = ig*16 + r;
        float a = sm[jl][i_local];
        __nv_bfloat16 h, l; bf16_split(a, h, l);
        size_t idx = ((size_t)b*TT + i0 + i_local)*TT + j0 + jl;
        g_ath[idx] = h;
        g_atl[idx] = l;
    }
    if (tid < 64)
        g_rsp[((size_t)b*TT + i0 + tid)*16 + (j0 >> 6)] =
            s2[0][tid] + s2[1][tid] + s2[2][tid] + s2[3][tid];
}

// ---------------- rowsum reduce over j-tile partials -------------------------
__global__ void k_rowsum2() {
    int row = blockIdx.x * 256 + threadIdx.x;   // b*T + i
    int il = row & 1023;
    int ntile = il >> 6;
    const float* p = &g_rsp[(size_t)row*16];
    float s = 0.f;
    for (int k = 0; k <= ntile; k++) s += p[k];
    g_rowsum[row] = s;
}

// ---------------- weight_x = softmax_t(rowsum) -------------------------------
__global__ void k_wx() {
    int b = blockIdx.x, tid = threadIdx.x;
    __shared__ float sm[256];
    float v[4], e[4];
    float mx = -1e30f;
#pragma unroll
    for (int r = 0; r < 4; r++) {
        v[r] = g_rowsum[b*TT + tid + r*256];
        mx = fmaxf(mx, v[r]);
    }
    sm[tid] = mx; __syncthreads();
    for (int s = 128; s > 0; s >>= 1) {
        if (tid < s) sm[tid] = fmaxf(sm[tid], sm[tid+s]);
        __syncthreads();
    }
    mx = sm[0]; __syncthreads();
    float sum = 0.f;
#pragma unroll
    for (int r = 0; r < 4; r++) { e[r] = __expf(v[r] - mx); sum += e[r]; }
    sm[tid] = sum; __syncthreads();
    for (int s = 128; s > 0; s >>= 1) {
        if (tid < s) sm[tid] += sm[tid+s];
        __syncthreads();
    }
    float rz = 1.f / sm[0];
#pragma unroll
    for (int r = 0; r < 4; r++) g_wx[b*TT + tid + r*256] = e[r] * rz;
}

// ---------------- av GEMM: h1[i][c] = attn @ v, banded K ---------------------
__global__ void __launch_bounds__(256, 2) k_av_mma() {
    extern __shared__ __align__(16) char smem[];
    int m0 = blockIdx.x * 128;
    int n0 = blockIdx.y * 64;
    int b = m0 >> 10, t0 = m0 & 1023;
    int tid = threadIdx.x;
    int wid = tid >> 5, lane = tid & 31;
    int warp_m = wid & 3, warp_n = wid >> 2;
    int g = lane >> 2, tg = lane & 3;
    u32 sbase = smem_u32(smem);
    int arow = tid >> 1, ahalf = tid & 1;
    int brow = tid >> 2, bq4 = tid & 3;

    float acc[2][4][4];
#pragma unroll
    for (int a = 0; a < 2; a++)
#pragma unroll
        for (int c = 0; c < 4; c++)
#pragma unroll
            for (int d = 0; d < 4; d++) acc[a][c][d] = 0.f;

    const __nv_bfloat16* Ahp = g_ath + ((size_t)b*TT + t0)*TT;
    const __nv_bfloat16* Alp = g_atl + ((size_t)b*TT + t0)*TT;
    const __nv_bfloat16* Bhp = g_vth + ((size_t)b*CC + n0)*TT;
    const __nv_bfloat16* Blp = g_vtl + ((size_t)b*CC + n0)*TT;
    int nch = (t0 + 128) >> 5;

#define ISSUE(cc, st) do {                                                    \
        size_t ga = (size_t)arow*TT + (cc)*32 + ahalf*16;                     \
        u32 da = (st) + arow*ROWB + ahalf*32;                                 \
        cp16(da,              Ahp + ga,     true);                            \
        cp16(da + 16,         Ahp + ga + 8, true);                            \
        cp16(da + A_MATB,     Alp + ga,     true);                            \
        cp16(da + A_MATB+16,  Alp + ga + 8, true);                            \
        size_t gb = (size_t)brow*TT + (cc)*32 + bq4*8;                        \
        u32 db = (st) + 2*A_MATB + brow*ROWB + bq4*16;                        \
        cp16(db,          Bhp + gb, true);                                    \
        cp16(db + B_MATB, Blp + gb, true);                                    \
    } while (0)

    MMA_MAINLOOP(nch)
#undef ISSUE

#pragma unroll
    for (int mt = 0; mt < 2; mt++) {
        int m_lo = m0 + warp_m*32 + mt*16 + g;
#pragma unroll
        for (int nt = 0; nt < 4; nt++) {
            int n = n0 + warp_n*32 + nt*8 + tg*2;
            float* c = acc[mt][nt];
            __nv_bfloat16 h0,l0,h1,l1;
            size_t i_lo = (size_t)m_lo*CC + n;
            size_t i_hi = (size_t)(m_lo+8)*CC + n;
            bf16_split(c[0], h0, l0); bf16_split(c[1], h1, l1);
            *(__nv_bfloat162*)&g_h1h[i_lo] = __nv_bfloat162(h0, h1);
            *(__nv_bfloat162*)&g_h1l[i_lo] = __nv_bfloat162(l0, l1);
            bf16_split(c[2], h0, l0); bf16_split(c[3], h1, l1);
            *(__nv_bfloat162*)&g_h1h[i_hi] = __nv_bfloat162(h0, h1);
            *(__nv_bfloat162*)&g_h1l[i_hi] = __nv_bfloat162(l0, l1);
        }
    }
}

// ---------------- conv GEMM --------------------------------------------------
__global__ void __launch_bounds__(256, 2) k_conv_mma(int mode,
                                                     const float* __restrict__ bias,
                                                     const float* __restrict__ x,
                                                     float* __restrict__ outp) {
    extern __shared__ __align__(16) char smem[];
    const __nv_bfloat16* Ahp = mode ? g_h2h  : g_h1h;
    const __nv_bfloat16* Alp = mode ? g_h2l  : g_h1l;
    const __nv_bfloat16* Bhp = mode ? g_w2bh : g_w1bh;
    const __nv_bfloat16* Blp = mode ? g_w2bl : g_w1bl;

    int m0 = blockIdx.x * 128;
    int n0 = blockIdx.y * 64;
    int b = m0 >> 10, t0 = m0 & 1023;
    int tid = threadIdx.x;
    int wid = tid >> 5, lane = tid & 31;
    int warp_m = wid & 3, warp_n = wid >> 2;
    int g = lane >> 2, tg = lane & 3;
    u32 sbase = smem_u32(smem);
    int arow = tid >> 1, ahalf = tid & 1;
    int brow = tid >> 2, bq4 = tid & 3;

    float acc[2][4][4];
#pragma unroll
    for (int a = 0; a < 2; a++)
#pragma unroll
        for (int c = 0; c < 4; c++)
#pragma unroll
            for (int d = 0; d < 4; d++) acc[a][c][d] = 0.f;

#define ISSUE(cc, st) do {                                                    \
        int koff = (cc) >> 3, i0c = ((cc) & 7) * 32;                          \
        int t = t0 + arow + koff - 2;                                         \
        bool ok = (t >= 0);                                                   \
        size_t ga = (size_t)(b*TT + t)*CC + i0c + ahalf*16;                   \
        u32 da = (st) + arow*ROWB + ahalf*32;                                 \
        cp16(da,              Ahp + ga,     ok);                              \
        cp16(da + 16,         Ahp + ga + 8, ok);                              \
        cp16(da + A_MATB,     Alp + ga,     ok);                              \
        cp16(da + A_MATB+16,  Alp + ga + 8, ok);                              \
        size_t gb = (size_t)(n0 + brow)*CONVK + (cc)*32 + bq4*8;              \
        u32 db = (st) + 2*A_MATB + brow*ROWB + bq4*16;                        \
        cp16(db,          Bhp + gb, true);                                    \
        cp16(db + B_MATB, Blp + gb, true);                                    \
    } while (0)

    MMA_MAINLOOP(24)
#undef ISSUE

#pragma unroll
    for (int mt = 0; mt < 2; mt++) {
        int t_lo = t0 + warp_m*32 + mt*16 + g;
        int t_hi = t_lo + 8;
        if (mode == 0) {
#pragma unroll
            for (int nt = 0; nt < 4; nt++) {
                int n = n0 + warp_n*32 + nt*8 + tg*2;
                float b0 = bias[n], b1 = bias[n+1];
                float* c = acc[mt][nt];
                float v0 = fmaxf(c[0] + b0, 0.f);
                float v1 = fmaxf(c[1] + b1, 0.f);
                float v2 = fmaxf(c[2] + b0, 0.f);
                float v3 = fmaxf(c[3] + b1, 0.f);
                __nv_bfloat16 h0,l0,h1,l1;
                bf16_split(v0, h0, l0); bf16_split(v1, h1, l1);
                size_t i_lo = (size_t)(b*TT + t_lo)*CC + n;
                *(__nv_bfloat162*)&g_h2h[i_lo] = __nv_bfloat162(h0, h1);
                *(__nv_bfloat162*)&g_h2l[i_lo] = __nv_bfloat162(l0, l1);
                bf16_split(v2, h0, l0); bf16_split(v3, h1, l1);
                size_t i_hi = (size_t)(b*TT + t_hi)*CC + n;
                *(__nv_bfloat162*)&g_h2h[i_hi] = __nv_bfloat162(h0, h1);
                *(__nv_bfloat162*)&g_h2l[i_hi] = __nv_bfloat162(l0, l1);
            }
        } else {
            float w_lo = 1.f + g_wx[b*TT + t_lo];
            float w_hi = 1.f + g_wx[b*TT + t_hi];
#pragma unroll
            for (int nt = 0; nt < 4; nt++) {
                int n = n0 + warp_n*32 + nt*8 + tg*2;
                float b0 = bias[n], b1 = bias[n+1];
                float* c = acc[mt][nt];
                size_t o00 = ((size_t)b*CC + n)*TT + t_lo;
                size_t o10 = o00 + TT;
                size_t o01 = o00 + 8;
                size_t o11 = o10 + 8;
                outp[o00] = fmaxf(fmaxf(c[0] + b0, 0.f) + x[o00]*w_lo, 0.f);
                outp[o10] = fmaxf(fmaxf(c[1] + b1, 0.f) + x[o10]*w_lo, 0.f);
                outp[o01] = fmaxf(fmaxf(c[2] + b0, 0.f) + x[o01]*w_hi, 0.f);
                outp[o11] = fmaxf(fmaxf(c[3] + b1, 0.f) + x[o11]*w_hi, 0.f);
            }
        }
    }
}

// ---------------- launch ------------------------------------------------------
extern "C" void kernel_launch(void* const* d_in, const int* in_sizes, int n_in,
                              void* d_out, int out_size) {
    const float* x  = (const float*)d_in[0];
    const float* wq = (const float*)d_in[1];
    const float* bq = (const float*)d_in[2];
    const float* wk = (const float*)d_in[3];
    const float* bk = (const float*)d_in[4];
    const float* wv = (const float*)d_in[5];
    const float* bv = (const float*)d_in[6];
    const float* v1 = (const float*)d_in[7];
    const float* g1 = (const float*)d_in[8];
    const float* b1 = (const float*)d_in[9];
    const float* v2 = (const float*)d_in[10];
    const float* g2 = (const float*)d_in[11];
    const float* b2 = (const float*)d_in[12];
    float* out = (float*)d_out;

    static int smset = 0;
    if (!smset) {
        cudaFuncSetAttribute(k_qkv_mma,    cudaFuncAttributeMaxDynamicSharedMemorySize, MMA_SMEM);
        cudaFuncSetAttribute(k_scores_mma, cudaFuncAttributeMaxDynamicSharedMemorySize, MMA_SMEM);
        cudaFuncSetAttribute(k_av_mma,     cudaFuncAttributeMaxDynamicSharedMemorySize, MMA_SMEM);
        cudaFuncSetAttribute(k_conv_mma,   cudaFuncAttributeMaxDynamicSharedMemorySize, MMA_SMEM);
        smset = 1;
    }

    k_prep_xt<<<dim3(TT/32, CC/32, BB), 256>>>(x);
    k_prep_wcat<<<QKVW, 256>>>(wq, bq, wk, bk, wv, bv);
    k_prep_convw<<<512, 256>>>(v1, g1, v2, g2);
    k_qkv_mma<<<dim3(MT/128, QKVW/64), 256, MMA_SMEM>>>();
    k_scores_mma<<<dim3(16, 8, BB), 256, MMA_SMEM>>>();
    k_stats<<<MT, 128>>>();
    k_attn_t<<<dim3(16, 16, BB), 256>>>();
    k_rowsum2<<<MT/256, 256>>>();
    k_wx<<<BB, 256>>>();
    k_av_mma<<<dim3(MT/128, CC/64), 256, MMA_SMEM>>>();
    k_conv_mma<<<dim3(MT/128, CC/64), 256, MMA_SMEM>>>(0, b1, x, out);
    k_conv_mma<<<dim3(MT/128, CC/64), 256, MMA_SMEM>>>(1, b2, x, out);
}

// round 7
// speedup vs baseline: 2.9037x; 1.0771x over previous
#include <cuda_runtime.h>
#include <cuda_bf16.h>
#include <cstdint>

#define BB 32
#define CC 256
#define TT 1024
#define QKVW 384
#define MT (BB*TT)
#define CONVK 768

typedef uint32_t u32;

// ---------------- scratch (device globals; zero-initialized BSS) -------------
__device__ float g_bcat[QKVW];
__device__ float g_st[(size_t)BB*TT*TT];     // scores [b][j][i]
__device__ float g_m[MT];
__device__ float g_rz[MT];
__device__ float g_rsp[(size_t)MT*16];       // rowsum partials per j-tile
__device__ float g_rowsum[MT];
__device__ float g_wx[MT];
// bf16 split operands
__device__ __align__(16) __nv_bfloat16 g_xth[(size_t)MT*CC];  // x^T [t][c]
__device__ __align__(16) __nv_bfloat16 g_xtl[(size_t)MT*CC];
__device__ __align__(16) __nv_bfloat16 g_wcbh[QKVW*CC];       // wcat^T [n][c]
__device__ __align__(16) __nv_bfloat16 g_wcbl[QKVW*CC];
__device__ __align__(16) __nv_bfloat16 g_qh[(size_t)MT*64];
__device__ __align__(16) __nv_bfloat16 g_ql[(size_t)MT*64];
__device__ __align__(16) __nv_bfloat16 g_kh[(size_t)MT*64];
__device__ __align__(16) __nv_bfloat16 g_kl[(size_t)MT*64];
__device__ __align__(16) __nv_bfloat16 g_vth[(size_t)BB*CC*TT]; // v^T [b][c][t]
__device__ __align__(16) __nv_bfloat16 g_vtl[(size_t)BB*CC*TT];
__device__ __align__(16) __nv_bfloat16 g_ath[(size_t)BB*TT*TT]; // attn [b][i][j]
__device__ __align__(16) __nv_bfloat16 g_atl[(size_t)BB*TT*TT]; // unwritten = 0
__device__ __align__(16) __nv_bfloat16 g_h1h[(size_t)MT*CC];
__device__ __align__(16) __nv_bfloat16 g_h1l[(size_t)MT*CC];
__device__ __align__(16) __nv_bfloat16 g_h2h[(size_t)MT*CC];
__device__ __align__(16) __nv_bfloat16 g_h2l[(size_t)MT*CC];
__device__ __align__(16) __nv_bfloat16 g_w1bh[CC*CONVK];
__device__ __align__(16) __nv_bfloat16 g_w1bl[CC*CONVK];
__device__ __align__(16) __nv_bfloat16 g_w2bh[CC*CONVK];
__device__ __align__(16) __nv_bfloat16 g_w2bl[CC*CONVK];

// ---------------- helpers ----------------------------------------------------
__device__ __forceinline__ u32 smem_u32(const void* p) {
    u32 a;
    asm("{ .reg .u64 t; cvta.to.shared.u64 t, %1; cvt.u32.u64 %0, t; }"
        : "=r"(a) : "l"(p));
    return a;
}
__device__ __forceinline__ void cp16(u32 dst, const void* src, bool ok) {
    int sz = ok ? 16 : 0;
    asm volatile("cp.async.cg.shared.global [%0], [%1], 16, %2;"
                 :: "r"(dst), "l"(src), "r"(sz) : "memory");
}
#define CP_COMMIT() asm volatile("cp.async.commit_group;" ::: "memory")
#define CP_WAIT1()  asm volatile("cp.async.wait_group 1;" ::: "memory")
#define CP_WAIT0()  asm volatile("cp.async.wait_group 0;" ::: "memory")

__device__ __forceinline__ void mma16816(float c[4], const u32 a[4], const u32 b[2]) {
    asm volatile(
        "mma.sync.aligned.m16n8k16.row.col.f32.bf16.bf16.f32 "
        "{%0,%1,%2,%3}, {%4,%5,%6,%7}, {%8,%9}, {%0,%1,%2,%3};"
        : "+f"(c[0]), "+f"(c[1]), "+f"(c[2]), "+f"(c[3])
        : "r"(a[0]), "r"(a[1]), "r"(a[2]), "r"(a[3]), "r"(b[0]), "r"(b[1]));
}
__device__ __forceinline__ void ldsm4(u32& r0, u32& r1, u32& r2, u32& r3, u32 addr) {
    asm volatile("ldmatrix.sync.aligned.m8n8.x4.shared.b16 {%0,%1,%2,%3}, [%4];"
                 : "=r"(r0), "=r"(r1), "=r"(r2), "=r"(r3) : "r"(addr));
}
__device__ __forceinline__ void bf16_split(float v, __nv_bfloat16& h, __nv_bfloat16& l) {
    h = __float2bfloat16(v);
    l = __float2bfloat16(v - __bfloat162float(h));
}

// ---- stage geometry: A 128 rows x 32K (h,l) + B 64 rows x 32K (h,l) ---------
#define ROWB 80
#define A_MATB (128*ROWB)      // 10240
#define B_MATB (64*ROWB)       // 5120
#define STG (2*A_MATB + 2*B_MATB)   // 30720
#define MMA_SMEM (3*STG)       // 92160 -> 2 CTAs/SM

// one K=32 chunk via ldmatrix: warp tile 32(M) x 32(N)
__device__ __forceinline__ void mma_chunk4(u32 base, u32 aoff, u32 boff,
                                           float acc[2][4][4]) {
#pragma unroll
    for (int ks = 0; ks < 2; ks++) {
        u32 ah[2][4], al[2][4];
#pragma unroll
        for (int mt = 0; mt < 2; mt++) {
            u32 ad = base + aoff + mt*(16*ROWB) + ks*32;
            ldsm4(ah[mt][0], ah[mt][1], ah[mt][2], ah[mt][3], ad);
            ldsm4(al[mt][0], al[mt][1], al[mt][2], al[mt][3], ad + A_MATB);
        }
        u32 bh[4][2], bl[4][2];
#pragma unroll
        for (int pr = 0; pr < 2; pr++) {
            u32 bd = base + 2*A_MATB + boff + pr*(16*ROWB) + ks*32;
            u32 r0, r1, r2, r3;
            ldsm4(r0, r1, r2, r3, bd);
            bh[2*pr][0] = r0; bh[2*pr][1] = r1;
            bh[2*pr+1][0] = r2; bh[2*pr+1][1] = r3;
            ldsm4(r0, r1, r2, r3, bd + B_MATB);
            bl[2*pr][0] = r0; bl[2*pr][1] = r1;
            bl[2*pr+1][0] = r2; bl[2*pr+1][1] = r3;
        }
#pragma unroll
        for (int mt = 0; mt < 2; mt++)
#pragma unroll
            for (int nt = 0; nt < 4; nt++) {
                mma16816(acc[mt][nt], ah[mt], bh[nt]);
                mma16816(acc[mt][nt], ah[mt], bl[nt]);
                mma16816(acc[mt][nt], al[mt], bh[nt]);
            }
    }
}

// per-warp ldmatrix address offsets (within a stage)
#define LDSM_OFFS()                                                           \
    u32 aoff = (u32)((warp_m*32 + (lane & 15))*ROWB + (lane >> 4)*16);        \
    u32 boff = (u32)((warp_n*32 + ((lane >> 4) << 3) + (lane & 7))*ROWB       \
                     + ((lane >> 3) & 1)*16);

// shared mainloop macro: ISSUE(cc, stage_u32_base) must cp all 4 matrices
#define MMA_MAINLOOP(NCH)                                                     \
    { ISSUE(0, sbase); } CP_COMMIT();                                         \
    { ISSUE(1, sbase + STG); } CP_COMMIT();                                   \
    for (int cc = 0; cc < (NCH); cc++) {                                      \
        int s = cc % 3;                                                       \
        if (cc + 1 < (NCH)) { CP_WAIT1(); } else { CP_WAIT0(); }              \
        __syncthreads();                                                      \
        mma_chunk4(sbase + s*STG, aoff, boff, acc);                           \
        if (cc + 2 < (NCH)) {                                                 \
            int s2 = (s + 2) % 3;                                             \
            ISSUE(cc + 2, sbase + s2*STG);                                    \
            CP_COMMIT();                                                      \
        }                                                                     \
    }

// ---------------- prep: transpose-split x ------------------------------------
__global__ void k_prep_xt(const float* __restrict__ x) {
    __shared__ float sm[32][33];
    int t0 = blockIdx.x * 32, c0 = blockIdx.y * 32, b = blockIdx.z;
    int lane = threadIdx.x & 31, grp = threadIdx.x >> 5;
#pragma unroll
    for (int r = 0; r < 4; r++) {
        int c = grp + r*8;
        sm[c][lane] = x[((size_t)b*CC + c0 + c)*TT + t0 + lane];
    }
    __syncthreads();
#pragma unroll
    for (int r = 0; r < 4; r++) {
        int t = grp + r*8;
        float v = sm[lane][t];
        __nv_bfloat16 h, l; bf16_split(v, h, l);
        size_t idx = (size_t)(b*TT + t0 + t)*CC + c0 + lane;
        g_xth[idx] = h; g_xtl[idx] = l;
    }
}

// ---------------- prep: wcat^T split + bcat ----------------------------------
__global__ void k_prep_wcat(const float* __restrict__ wq, const float* __restrict__ bq,
                            const float* __restrict__ wk, const float* __restrict__ bk,
                            const float* __restrict__ wv, const float* __restrict__ bv) {
    int n = blockIdx.x;
    int c = threadIdx.x;
    float w;
    if (n < 64)       w = wq[c*64 + n];
    else if (n < 128) w = wk[c*64 + (n-64)];
    else              w = wv[c*256 + (n-128)];
    __nv_bfloat16 h, l; bf16_split(w, h, l);
    g_wcbh[n*CC + c] = h;
    g_wcbl[n*CC + c] = l;
    if (c == 0)
        g_bcat[n] = (n < 64) ? bq[n] : (n < 128) ? bk[n-64] : bv[n-128];
}

// ---------------- prep: weight-norm conv weights -----------------------------
__global__ void k_prep_convw(const float* __restrict__ v1, const float* __restrict__ g1,
                             const float* __restrict__ v2, const float* __restrict__ g2) {
    int layer = blockIdx.x >> 8;
    int o = blockIdx.x & 255;
    const float* v = layer ? v2 : v1;
    const float* g = layer ? g2 : g1;
    __nv_bfloat16* wh = layer ? g_w2bh : g_w1bh;
    __nv_bfloat16* wl = layer ? g_w2bl : g_w1bl;
    int tid = threadIdx.x;
    float vv[3];
    float part = 0.f;
#pragma unroll
    for (int k = 0; k < 3; k++) {
        vv[k] = v[((size_t)o*CC + tid)*3 + k];
        part += vv[k]*vv[k];
    }
    __shared__ float sm[256];
    sm[tid] = part; __syncthreads();
    for (int s = 128; s > 0; s >>= 1) {
        if (tid < s) sm[tid] += sm[tid+s];
        __syncthreads();
    }
    float scale = g[o] * rsqrtf(sm[0]);
#pragma unroll
    for (int k = 0; k < 3; k++) {
        float w = scale * vv[k];
        __nv_bfloat16 h, l; bf16_split(w, h, l);
        wh[(size_t)o*CONVK + k*CC + tid] = h;
        wl[(size_t)o*CONVK + k*CC + tid] = l;
    }
}

// ---------------- qkv GEMM -----------------------------------------------------
__global__ void __launch_bounds__(256, 2) k_qkv_mma() {
    extern __shared__ __align__(16) char smem[];
    int m0 = blockIdx.x * 128;
    int n0 = blockIdx.y * 64;
    int tid = threadIdx.x;
    int wid = tid >> 5, lane = tid & 31;
    int warp_m = wid & 3, warp_n = wid >> 2;
    int g = lane >> 2, tg = lane & 3;
    u32 sbase = smem_u32(smem);
    int arow = tid >> 1, ahalf = tid & 1;
    int brow = tid >> 2, bq4 = tid & 3;
    LDSM_OFFS()

    float acc[2][4][4];
#pragma unroll
    for (int a = 0; a < 2; a++)
#pragma unroll
        for (int c = 0; c < 4; c++)
#pragma unroll
            for (int d = 0; d < 4; d++) acc[a][c][d] = 0.f;

#define ISSUE(cc, st) do {                                                    \
        size_t ga = (size_t)(m0 + arow)*CC + (cc)*32 + ahalf*16;              \
        u32 da = (st) + arow*ROWB + ahalf*32;                                 \
        cp16(da,              g_xth + ga,     true);                          \
        cp16(da + 16,         g_xth + ga + 8, true);                          \
        cp16(da + A_MATB,     g_xtl + ga,     true);                          \
        cp16(da + A_MATB+16,  g_xtl + ga + 8, true);                          \
        size_t gb = (size_t)(n0 + brow)*CC + (cc)*32 + bq4*8;                 \
        u32 db = (st) + 2*A_MATB + brow*ROWB + bq4*16;                        \
        cp16(db,          g_wcbh + gb, true);                                 \
        cp16(db + B_MATB, g_wcbl + gb, true);                                 \
    } while (0)

    MMA_MAINLOOP(8)
#undef ISSUE

    int b = m0 >> 10, t0 = m0 & 1023;
#pragma unroll
    for (int mt = 0; mt < 2; mt++) {
        int mr = warp_m*32 + mt*16 + g;
#pragma unroll
        for (int nt = 0; nt < 4; nt++) {
            int n = n0 + warp_n*32 + nt*8 + tg*2;
            float* c = acc[mt][nt];
            float v00 = c[0] + g_bcat[n],   v01 = c[1] + g_bcat[n+1];
            float v10 = c[2] + g_bcat[n],   v11 = c[3] + g_bcat[n+1];
            __nv_bfloat16 h0,l0,h1,l1;
            if (n < 128) {
                __nv_bfloat16* ph = (n < 64) ? g_qh : g_kh;
                __nv_bfloat16* pl = (n < 64) ? g_ql : g_kl;
                int nn = n & 63;
                size_t i_lo = (size_t)(m0 + mr)*64 + nn;
                size_t i_hi = (size_t)(m0 + mr + 8)*64 + nn;
                bf16_split(v00, h0, l0); bf16_split(v01, h1, l1);
                *(__nv_bfloat162*)&ph[i_lo] = __nv_bfloat162(h0, h1);
                *(__nv_bfloat162*)&pl[i_lo] = __nv_bfloat162(l0, l1);
                bf16_split(v10, h0, l0); bf16_split(v11, h1, l1);
                *(__nv_bfloat162*)&ph[i_hi] = __nv_bfloat162(h0, h1);
                *(__nv_bfloat162*)&pl[i_hi] = __nv_bfloat162(l0, l1);
            } else {
                int cch = n - 128;
                int t_lo = t0 + mr, t_hi = t_lo + 8;
                size_t b00 = ((size_t)b*CC + cch)*TT;
                bf16_split(v00, h0, l0);
                g_vth[b00 + t_lo] = h0; g_vtl[b00 + t_lo] = l0;
                bf16_split(v10, h0, l0);
                g_vth[b00 + t_hi] = h0; g_vtl[b00 + t_hi] = l0;
                bf16_split(v01, h1, l1);
                g_vth[b00 + TT + t_lo] = h1; g_vtl[b00 + TT + t_lo] = l1;
                bf16_split(v11, h1, l1);
                g_vth[b00 + TT + t_hi] = h1; g_vtl[b00 + TT + t_hi] = l1;
            }
        }
    }
}

// ---------------- scores GEMM: st[b][j][i], band tiles only ------------------
__global__ void __launch_bounds__(256, 2) k_scores_mma() {
    int i0 = blockIdx.x * 64, j0 = blockIdx.y * 128, b = blockIdx.z;
    if (j0 > i0 + 63) return;
    extern __shared__ __align__(16) char smem[];
    int tid = threadIdx.x;
    int wid = tid >> 5, lane = tid & 31;
    int warp_m = wid & 3, warp_n = wid >> 2;
    int g = lane >> 2, tg = lane & 3;
    u32 sbase = smem_u32(smem);
    int arow = tid >> 1, ahalf = tid & 1;
    int brow = tid >> 2, bq4 = tid & 3;
    LDSM_OFFS()

    float acc[2][4][4];
#pragma unroll
    for (int a = 0; a < 2; a++)
#pragma unroll
        for (int c = 0; c < 4; c++)
#pragma unroll
            for (int d = 0; d < 4; d++) acc[a][c][d] = 0.f;

    const __nv_bfloat16* Ahp = g_kh + (size_t)(b*TT + j0)*64;
    const __nv_bfloat16* Alp = g_kl + (size_t)(b*TT + j0)*64;
    const __nv_bfloat16* Bhp = g_qh + (size_t)(b*TT + i0)*64;
    const __nv_bfloat16* Blp = g_ql + (size_t)(b*TT + i0)*64;

#define ISSUE(cc, st) do {                                                    \
        size_t ga = (size_t)arow*64 + (cc)*32 + ahalf*16;                     \
        u32 da = (st) + arow*ROWB + ahalf*32;                                 \
        cp16(da,              Ahp + ga,     true);                            \
        cp16(da + 16,         Ahp + ga + 8, true);                            \
        cp16(da + A_MATB,     Alp + ga,     true);                            \
        cp16(da + A_MATB+16,  Alp + ga + 8, true);                            \
        size_t gb = (size_t)brow*64 + (cc)*32 + bq4*8;                        \
        u32 db = (st) + 2*A_MATB + brow*ROWB + bq4*16;                        \
        cp16(db,          Bhp + gb, true);                                    \
        cp16(db + B_MATB, Blp + gb, true);                                    \
    } while (0)

    MMA_MAINLOOP(2)
#undef ISSUE

    size_t base = (size_t)b*TT*TT;
#pragma unroll
    for (int mt = 0; mt < 2; mt++) {
        int j_lo = j0 + warp_m*32 + mt*16 + g;
#pragma unroll
        for (int nt = 0; nt < 4; nt++) {
            int i = i0 + warp_n*32 + nt*8 + tg*2;
            float* c = acc[mt][nt];
            *(float2*)&g_st[base + (size_t)j_lo*TT + i] =
                make_float2(c[0]*0.125f, c[1]*0.125f);
            *(float2*)&g_st[base + (size_t)(j_lo+8)*TT + i] =
                make_float2(c[2]*0.125f, c[3]*0.125f);
        }
    }
}

// ---------------- per-(b,j) softmax stats over i in [j, T) -------------------
__global__ void k_stats() {
    int row = blockIdx.x;
    int b = row >> 10, j = row & 1023;
    const float* p = g_st + (size_t)b*TT*TT + (size_t)j*TT;
    int tid = threadIdx.x;
    __shared__ float sm[128];
    float mx = -1e30f;
    for (int i = j + tid; i < TT; i += 128) mx = fmaxf(mx, p[i]);
    sm[tid] = mx; __syncthreads();
    for (int s = 64; s > 0; s >>= 1) {
        if (tid < s) sm[tid] = fmaxf(sm[tid], sm[tid+s]);
        __syncthreads();
    }
    mx = sm[0]; __syncthreads();
    float sum = 0.f;
    for (int i = j + tid; i < TT; i += 128) sum += __expf(p[i] - mx);
    sm[tid] = sum; __syncthreads();
    for (int s = 64; s > 0; s >>= 1) {
        if (tid < s) sm[tid] += sm[tid+s];
        __syncthreads();
    }
    if (tid == 0) { g_m[row] = mx; g_rz[row] = 1.f / sm[0]; }
}

// ------- attn transpose-split + fused rowsum partials ------------------------
__global__ void __launch_bounds__(256) k_attn_t() {
    int i0 = blockIdx.x * 64, j0 = blockIdx.y * 64, b = blockIdx.z;
    if (j0 > i0) return;
    __shared__ float sm[64][65];
    __shared__ float s2[4][64];
    int tid = threadIdx.x;
    int il = tid & 63, jg = tid >> 6;
    size_t base = (size_t)b*TT*TT;
    float part = 0.f;
#pragma unroll 4
    for (int r = 0; r < 16; r++) {
        int j = j0 + jg*16 + r;
        float mj = g_m[b*TT + j];
        float rz = g_rz[b*TT + j];
        int i = i0 + il;
        float a = 0.f;
        if (i >= j) a = __expf(g_st[base + (size_t)j*TT + i] - mj) * rz;
        sm[jg*16 + r][il] = a;
        part += a;
    }
    s2[jg][il] = part;
    __syncthreads();
    int jl = tid & 63, ig = tid >> 6;
#pragma unroll 4
    for (int r = 0; r < 16; r++) {
        int i_local = ig*16 + r;
        float a = sm[jl][i_local];
        __nv_bfloat16 h, l; bf16_split(a, h, l);
        size_t idx = ((size_t)b*TT + i0 + i_local)*TT + j0 + jl;
        g_ath[idx] = h;
        g_atl[idx] = l;
    }
    if (tid < 64)
        g_rsp[((size_t)b*TT + i0 + tid)*16 + (j0 >> 6)] =
            s2[0][tid] + s2[1][tid] + s2[2][tid] + s2[3][tid];
}

// ---------------- rowsum reduce over j-tile partials -------------------------
__global__ void k_rowsum2() {
    int row = blockIdx.x * 256 + threadIdx.x;   // b*T + i
    int il = row & 1023;
    int ntile = il >> 6;
    const float* p = &g_rsp[(size_t)row*16];
    float s = 0.f;
    for (int k = 0; k <= ntile; k++) s += p[k];
    g_rowsum[row] = s;
}

// ---------------- weight_x = softmax_t(rowsum) -------------------------------
__global__ void k_wx() {
    int b = blockIdx.x, tid = threadIdx.x;
    __shared__ float sm[256];
    float v[4], e[4];
    float mx = -1e30f;
#pragma unroll
    for (int r = 0; r < 4; r++) {
        v[r] = g_rowsum[b*TT + tid + r*256];
        mx = fmaxf(mx, v[r]);
    }
    sm[tid] = mx; __syncthreads();
    for (int s = 128; s > 0; s >>= 1) {
        if (tid < s) sm[tid] = fmaxf(sm[tid], sm[tid+s]);
        __syncthreads();
    }
    mx = sm[0]; __syncthreads();
    float sum = 0.f;
#pragma unroll
    for (int r = 0; r < 4; r++) { e[r] = __expf(v[r] - mx); sum += e[r]; }
    sm[tid] = sum; __syncthreads();
    for (int s = 128; s > 0; s >>= 1) {
        if (tid < s) sm[tid] += sm[tid+s];
        __syncthreads();
    }
    float rz = 1.f / sm[0];
#pragma unroll
    for (int r = 0; r < 4; r++) g_wx[b*TT + tid + r*256] = e[r] * rz;
}

// ---------------- av GEMM: h1[i][c] = attn @ v, banded K ---------------------
__global__ void __launch_bounds__(256, 2) k_av_mma() {
    extern __shared__ __align__(16) char smem[];
    int m0 = blockIdx.x * 128;
    int n0 = blockIdx.y * 64;
    int b = m0 >> 10, t0 = m0 & 1023;
    int tid = threadIdx.x;
    int wid = tid >> 5, lane = tid & 31;
    int warp_m = wid & 3, warp_n = wid >> 2;
    int g = lane >> 2, tg = lane & 3;
    u32 sbase = smem_u32(smem);
    int arow = tid >> 1, ahalf = tid & 1;
    int brow = tid >> 2, bq4 = tid & 3;
    LDSM_OFFS()

    float acc[2][4][4];
#pragma unroll
    for (int a = 0; a < 2; a++)
#pragma unroll
        for (int c = 0; c < 4; c++)
#pragma unroll
            for (int d = 0; d < 4; d++) acc[a][c][d] = 0.f;

    const __nv_bfloat16* Ahp = g_ath + ((size_t)b*TT + t0)*TT;
    const __nv_bfloat16* Alp = g_atl + ((size_t)b*TT + t0)*TT;
    const __nv_bfloat16* Bhp = g_vth + ((size_t)b*CC + n0)*TT;
    const __nv_bfloat16* Blp = g_vtl + ((size_t)b*CC + n0)*TT;
    int nch = (t0 + 128) >> 5;

#define ISSUE(cc, st) do {                                                    \
        size_t ga = (size_t)arow*TT + (cc)*32 + ahalf*16;                     \
        u32 da = (st) + arow*ROWB + ahalf*32;                                 \
        cp16(da,              Ahp + ga,     true);                            \
        cp16(da + 16,         Ahp + ga + 8, true);                            \
        cp16(da + A_MATB,     Alp + ga,     true);                            \
        cp16(da + A_MATB+16,  Alp + ga + 8, true);                            \
        size_t gb = (size_t)brow*TT + (cc)*32 + bq4*8;                        \
        u32 db = (st) + 2*A_MATB + brow*ROWB + bq4*16;                        \
        cp16(db,          Bhp + gb, true);                                    \
        cp16(db + B_MATB, Blp + gb, true);                                    \
    } while (0)

    MMA_MAINLOOP(nch)
#undef ISSUE

#pragma unroll
    for (int mt = 0; mt < 2; mt++) {
        int m_lo = m0 + warp_m*32 + mt*16 + g;
#pragma unroll
        for (int nt = 0; nt < 4; nt++) {
            int n = n0 + warp_n*32 + nt*8 + tg*2;
            float* c = acc[mt][nt];
            __nv_bfloat16 h0,l0,h1,l1;
            size_t i_lo = (size_t)m_lo*CC + n;
            size_t i_hi = (size_t)(m_lo+8)*CC + n;
            bf16_split(c[0], h0, l0); bf16_split(c[1], h1, l1);
            *(__nv_bfloat162*)&g_h1h[i_lo] = __nv_bfloat162(h0, h1);
            *(__nv_bfloat162*)&g_h1l[i_lo] = __nv_bfloat162(l0, l1);
            bf16_split(c[2], h0, l0); bf16_split(c[3], h1, l1);
            *(__nv_bfloat162*)&g_h1h[i_hi] = __nv_bfloat162(h0, h1);
            *(__nv_bfloat162*)&g_h1l[i_hi] = __nv_bfloat162(l0, l1);
        }
    }
}

// ---------------- conv GEMM --------------------------------------------------
__global__ void __launch_bounds__(256, 2) k_conv_mma(int mode,
                                                     const float* __restrict__ bias,
                                                     const float* __restrict__ x,
                                                     float* __restrict__ outp) {
    extern __shared__ __align__(16) char smem[];
    const __nv_bfloat16* Ahp = mode ? g_h2h  : g_h1h;
    const __nv_bfloat16* Alp = mode ? g_h2l  : g_h1l;
    const __nv_bfloat16* Bhp = mode ? g_w2bh : g_w1bh;
    const __nv_bfloat16* Blp = mode ? g_w2bl : g_w1bl;

    int m0 = blockIdx.x * 128;
    int n0 = blockIdx.y * 64;
    int b = m0 >> 10, t0 = m0 & 1023;
    int tid = threadIdx.x;
    int wid = tid >> 5, lane = tid & 31;
    int warp_m = wid & 3, warp_n = wid >> 2;
    int g = lane >> 2, tg = lane & 3;
    u32 sbase = smem_u32(smem);
    int arow = tid >> 1, ahalf = tid & 1;
    int brow = tid >> 2, bq4 = tid & 3;
    LDSM_OFFS()

    float acc[2][4][4];
#pragma unroll
    for (int a = 0; a < 2; a++)
#pragma unroll
        for (int c = 0; c < 4; c++)
#pragma unroll
            for (int d = 0; d < 4; d++) acc[a][c][d] = 0.f;

#define ISSUE(cc, st) do {                                                    \
        int koff = (cc) >> 3, i0c = ((cc) & 7) * 32;                          \
        int t = t0 + arow + koff - 2;                                         \
        bool ok = (t >= 0);                                                   \
        size_t ga = (size_t)(b*TT + t)*CC + i0c + ahalf*16;                   \
        u32 da = (st) + arow*ROWB + ahalf*32;                                 \
        cp16(da,              Ahp + ga,     ok);                              \
        cp16(da + 16,         Ahp + ga + 8, ok);                              \
        cp16(da + A_MATB,     Alp + ga,     ok);                              \
        cp16(da + A_MATB+16,  Alp + ga + 8, ok);                              \
        size_t gb = (size_t)(n0 + brow)*CONVK + (cc)*32 + bq4*8;              \
        u32 db = (st) + 2*A_MATB + brow*ROWB + bq4*16;                        \
        cp16(db,          Bhp + gb, true);                                    \
        cp16(db + B_MATB, Blp + gb, true);                                    \
    } while (0)

    MMA_MAINLOOP(24)
#undef ISSUE

#pragma unroll
    for (int mt = 0; mt < 2; mt++) {
        int t_lo = t0 + warp_m*32 + mt*16 + g;
        int t_hi = t_lo + 8;
        if (mode == 0) {
#pragma unroll
            for (int nt = 0; nt < 4; nt++) {
                int n = n0 + warp_n*32 + nt*8 + tg*2;
                float b0 = bias[n], b1 = bias[n+1];
                float* c = acc[mt][nt];
                float v0 = fmaxf(c[0] + b0, 0.f);
                float v1 = fmaxf(c[1] + b1, 0.f);
                float v2 = fmaxf(c[2] + b0, 0.f);
                float v3 = fmaxf(c[3] + b1, 0.f);
                __nv_bfloat16 h0,l0,h1,l1;
                bf16_split(v0, h0, l0); bf16_split(v1, h1, l1);
                size_t i_lo = (size_t)(b*TT + t_lo)*CC + n;
                *(__nv_bfloat162*)&g_h2h[i_lo] = __nv_bfloat162(h0, h1);
                *(__nv_bfloat162*)&g_h2l[i_lo] = __nv_bfloat162(l0, l1);
                bf16_split(v2, h0, l0); bf16_split(v3, h1, l1);
                size_t i_hi = (size_t)(b*TT + t_hi)*CC + n;
                *(__nv_bfloat162*)&g_h2h[i_hi] = __nv_bfloat162(h0, h1);
                *(__nv_bfloat162*)&g_h2l[i_hi] = __nv_bfloat162(l0, l1);
            }
        } else {
            float w_lo = 1.f + g_wx[b*TT + t_lo];
            float w_hi = 1.f + g_wx[b*TT + t_hi];
#pragma unroll
            for (int nt = 0; nt < 4; nt++) {
                int n = n0 + warp_n*32 + nt*8 + tg*2;
                float b0 = bias[n], b1 = bias[n+1];
                float* c = acc[mt][nt];
                size_t o00 = ((size_t)b*CC + n)*TT + t_lo;
                size_t o10 = o00 + TT;
                size_t o01 = o00 + 8;
                size_t o11 = o10 + 8;
                outp[o00] = fmaxf(fmaxf(c[0] + b0, 0.f) + x[o00]*w_lo, 0.f);
                outp[o10] = fmaxf(fmaxf(c[1] + b1, 0.f) + x[o10]*w_lo, 0.f);
                outp[o01] = fmaxf(fmaxf(c[2] + b0, 0.f) + x[o01]*w_hi, 0.f);
                outp[o11] = fmaxf(fmaxf(c[3] + b1, 0.f) + x[o11]*w_hi, 0.f);
            }
        }
    }
}

// ---------------- launch ------------------------------------------------------
extern "C" void kernel_launch(void* const* d_in, const int* in_sizes, int n_in,
                              void* d_out, int out_size) {
    const float* x  = (const float*)d_in[0];
    const float* wq = (const float*)d_in[1];
    const float* bq = (const float*)d_in[2];
    const float* wk = (const float*)d_in[3];
    const float* bk = (const float*)d_in[4];
    const float* wv = (const float*)d_in[5];
    const float* bv = (const float*)d_in[6];
    const float* v1 = (const float*)d_in[7];
    const float* g1 = (const float*)d_in[8];
    const float* b1 = (const float*)d_in[9];
    const float* v2 = (const float*)d_in[10];
    const float* g2 = (const float*)d_in[11];
    const float* b2 = (const float*)d_in[12];
    float* out = (float*)d_out;

    static int smset = 0;
    if (!smset) {
        cudaFuncSetAttribute(k_qkv_mma,    cudaFuncAttributeMaxDynamicSharedMemorySize, MMA_SMEM);
        cudaFuncSetAttribute(k_scores_mma, cudaFuncAttributeMaxDynamicSharedMemorySize, MMA_SMEM);
        cudaFuncSetAttribute(k_av_mma,     cudaFuncAttributeMaxDynamicSharedMemorySize, MMA_SMEM);
        cudaFuncSetAttribute(k_conv_mma,   cudaFuncAttributeMaxDynamicSharedMemorySize, MMA_SMEM);
        smset = 1;
    }

    k_prep_xt<<<dim3(TT/32, CC/32, BB), 256>>>(x);
    k_prep_wcat<<<QKVW, 256>>>(wq, bq, wk, bk, wv, bv);
    k_prep_convw<<<512, 256>>>(v1, g1, v2, g2);
    k_qkv_mma<<<dim3(MT/128, QKVW/64), 256, MMA_SMEM>>>();
    k_scores_mma<<<dim3(16, 8, BB), 256, MMA_SMEM>>>();
    k_stats<<<MT, 128>>>();
    k_attn_t<<<dim3(16, 16, BB), 256>>>();
    k_rowsum2<<<MT/256, 256>>>();
    k_wx<<<BB, 256>>>();
    k_av_mma<<<dim3(MT/128, CC/64), 256, MMA_SMEM>>>();
    k_conv_mma<<<dim3(MT/128, CC/64), 256, MMA_SMEM>>>(0, b1, x, out);
    k_conv_mma<<<dim3(MT/128, CC/64), 256, MMA_SMEM>>>(1, b2, x, out);
}